// round 4
// baseline (speedup 1.0000x reference)
#include <cuda_runtime.h>
#include <cstdint>
#include <cstddef>

// Problem dims
#define BB   256      // batch
#define TT   512      // time
#define OBS  64
#define HH   256      // hidden
#define G3   768      // 3*H
#define HHQ  64       // HH/4 (k-quads)

typedef unsigned long long u64;

// ---------------- scratch (device globals: allocation-free) ----------------
__device__ float g_xg[(size_t)BB * TT * G3];   // 402 MB: gate pre-activations
__device__ float g_y0[(size_t)BB * TT * HH];   // 134 MB: layer-0 outputs
__device__ float g_wt[(size_t)HH * G3];        // 786 KB: transposed W_hh (k-major, quad-interleaved)

// ---------------- f32x2 packed-fp32 helpers (sm_100+) ----------------
__device__ __forceinline__ u64 dupf(float a) {
    u64 r; asm("mov.b64 %0, {%1,%1};" : "=l"(r) : "f"(a)); return r;
}
__device__ __forceinline__ u64 pk2(float lo, float hi) {
    u64 r; asm("mov.b64 %0, {%1,%2};" : "=l"(r) : "f"(lo), "f"(hi)); return r;
}
__device__ __forceinline__ float2 unpk(u64 v) {
    float2 f; asm("mov.b64 {%0,%1}, %2;" : "=f"(f.x), "=f"(f.y) : "l"(v)); return f;
}
__device__ __forceinline__ u64 f2fma(u64 a, u64 b, u64 c) {
    u64 d; asm("fma.rn.f32x2 %0, %1, %2, %3;" : "=l"(d) : "l"(a), "l"(b), "l"(c)); return d;
}
__device__ __forceinline__ float sigmf(float x) {
    return 1.0f / (1.0f + __expf(-x));
}
__device__ __forceinline__ float tanh_fast(float x) {
    // 1 - 2/(e^{2x}+1): exact limits at +-inf, ~1e-7 rel error via __expf
    return 1.0f - __fdividef(2.0f, __expf(2.0f * x) + 1.0f);
}

// =====================================================================
// W_hh transpose: Whh[g][k] (g-major) -> Wt4 quad-interleaved:
//   Wt4[(k>>2)*G3*4 + g*4 + (k&3)]  == float4 view: wt4v[k/4][g]
// =====================================================================
__global__ void transpose_whh(const float* __restrict__ W, float* __restrict__ Wt4)
{
    const int g = blockIdx.x;        // 0..767
    const int k = threadIdx.x;       // 0..255
    const float v = W[(size_t)g * HH + k];   // coalesced read
    Wt4[(size_t)(k >> 2) * (G3 * 4) + g * 4 + (k & 3)] = v;
}

// =====================================================================
// Projection GEMM: C[M][768] = A[M][K] @ W[768][K]^T + bias[768]
// =====================================================================
#define PBM 128
#define PBN 64
#define PBK 16

__global__ void __launch_bounds__(256) proj_kernel(
    const float* __restrict__ A, const float* __restrict__ Wt,
    const float* __restrict__ bias, float* __restrict__ C, int K)
{
    __shared__ float As[2][PBK][PBM];
    __shared__ float Wsf[2][PBK][PBN];

    const int tid = threadIdx.x;
    const int tx = tid & 15;
    const int ty = tid >> 4;
    const int m0 = blockIdx.y * PBM;
    const int n0 = blockIdx.x * PBN;

    const int lrow = tid >> 2;
    const int lk4  = (tid & 3) << 2;
    const float* Ag0 = A  + (size_t)(m0 + lrow)      * K + lk4;
    const float* Ag1 = A  + (size_t)(m0 + lrow + 64) * K + lk4;
    const float* Wg  = Wt + (size_t)(n0 + lrow)      * K + lk4;

    u64 acc[8][2];
    #pragma unroll
    for (int i = 0; i < 8; ++i) { acc[i][0] = 0ULL; acc[i][1] = 0ULL; }

    const int panels = K >> 4;
    {
        float4 va0 = *(const float4*)(Ag0);
        float4 va1 = *(const float4*)(Ag1);
        float4 vw  = *(const float4*)(Wg);
        As[0][lk4+0][lrow] = va0.x; As[0][lk4+1][lrow] = va0.y;
        As[0][lk4+2][lrow] = va0.z; As[0][lk4+3][lrow] = va0.w;
        As[0][lk4+0][lrow+64] = va1.x; As[0][lk4+1][lrow+64] = va1.y;
        As[0][lk4+2][lrow+64] = va1.z; As[0][lk4+3][lrow+64] = va1.w;
        Wsf[0][lk4+0][lrow] = vw.x; Wsf[0][lk4+1][lrow] = vw.y;
        Wsf[0][lk4+2][lrow] = vw.z; Wsf[0][lk4+3][lrow] = vw.w;
    }
    __syncthreads();

    for (int p = 0; p < panels; ++p) {
        const int buf = p & 1;
        float4 na0, na1, nw;
        const bool more = (p + 1 < panels);
        if (more) {
            const int k0 = (p + 1) << 4;
            na0 = *(const float4*)(Ag0 + k0);
            na1 = *(const float4*)(Ag1 + k0);
            nw  = *(const float4*)(Wg  + k0);
        }
        #pragma unroll
        for (int k = 0; k < PBK; ++k) {
            float4 a0 = *(const float4*)&As[buf][k][ty * 8];
            float4 a1 = *(const float4*)&As[buf][k][ty * 8 + 4];
            ulonglong2 w = *(const ulonglong2*)&Wsf[buf][k][tx * 4];
            u64 d;
            d = dupf(a0.x); acc[0][0]=f2fma(d,w.x,acc[0][0]); acc[0][1]=f2fma(d,w.y,acc[0][1]);
            d = dupf(a0.y); acc[1][0]=f2fma(d,w.x,acc[1][0]); acc[1][1]=f2fma(d,w.y,acc[1][1]);
            d = dupf(a0.z); acc[2][0]=f2fma(d,w.x,acc[2][0]); acc[2][1]=f2fma(d,w.y,acc[2][1]);
            d = dupf(a0.w); acc[3][0]=f2fma(d,w.x,acc[3][0]); acc[3][1]=f2fma(d,w.y,acc[3][1]);
            d = dupf(a1.x); acc[4][0]=f2fma(d,w.x,acc[4][0]); acc[4][1]=f2fma(d,w.y,acc[4][1]);
            d = dupf(a1.y); acc[5][0]=f2fma(d,w.x,acc[5][0]); acc[5][1]=f2fma(d,w.y,acc[5][1]);
            d = dupf(a1.z); acc[6][0]=f2fma(d,w.x,acc[6][0]); acc[6][1]=f2fma(d,w.y,acc[6][1]);
            d = dupf(a1.w); acc[7][0]=f2fma(d,w.x,acc[7][0]); acc[7][1]=f2fma(d,w.y,acc[7][1]);
        }
        if (more) {
            const int nb = buf ^ 1;
            As[nb][lk4+0][lrow] = na0.x; As[nb][lk4+1][lrow] = na0.y;
            As[nb][lk4+2][lrow] = na0.z; As[nb][lk4+3][lrow] = na0.w;
            As[nb][lk4+0][lrow+64] = na1.x; As[nb][lk4+1][lrow+64] = na1.y;
            As[nb][lk4+2][lrow+64] = na1.z; As[nb][lk4+3][lrow+64] = na1.w;
            Wsf[nb][lk4+0][lrow] = nw.x; Wsf[nb][lk4+1][lrow] = nw.y;
            Wsf[nb][lk4+2][lrow] = nw.z; Wsf[nb][lk4+3][lrow] = nw.w;
        }
        __syncthreads();
    }

    const float4 bv = *(const float4*)&bias[n0 + tx * 4];
    #pragma unroll
    for (int i = 0; i < 8; ++i) {
        float2 v0 = unpk(acc[i][0]);
        float2 v1 = unpk(acc[i][1]);
        float4 o;
        o.x = v0.x + bv.x; o.y = v0.y + bv.y;
        o.z = v1.x + bv.z; o.w = v1.y + bv.w;
        const int m = m0 + ty * 8 + i;
        *(float4*)&C[(size_t)m * G3 + n0 + tx * 4] = o;
    }
}

// =====================================================================
// Recurrent scan v3: 64 blocks x 384 threads; thread owns 2 gate-columns
// (tid, tid+384). Weights are the packed f32x2 operand (no dup movs);
// h stored per-batch in smem, broadcast-read as k-quads.
// W residency: quads [0,17) smem, [17,21) regs, [21,64) streamed from L2.
// =====================================================================
#define NT   384
#define KCQ  17                          // quads cached in smem (k < 68)
#define KRQ  4                           // quads cached in regs  (k 68..83)
#define KSQ0 (KCQ + KRQ)                 // first streamed quad (21)
#define SCAN_DSMEM (KCQ * G3 * 16)       // 208896 B

// 16 f2fma for one quad, both columns, all 4 batch rows
#define QUAD_FMA(wa, wb, h0, h1, h2, h3)                                   \
    do {                                                                   \
        aA0 = f2fma(wa.x, h0.x, aA0); aA0 = f2fma(wa.y, h0.y, aA0);        \
        aA1 = f2fma(wa.x, h1.x, aA1); aA1 = f2fma(wa.y, h1.y, aA1);        \
        aA2 = f2fma(wa.x, h2.x, aA2); aA2 = f2fma(wa.y, h2.y, aA2);        \
        aA3 = f2fma(wa.x, h3.x, aA3); aA3 = f2fma(wa.y, h3.y, aA3);        \
        aB0 = f2fma(wb.x, h0.x, aB0); aB0 = f2fma(wb.y, h0.y, aB0);        \
        aB1 = f2fma(wb.x, h1.x, aB1); aB1 = f2fma(wb.y, h1.y, aB1);        \
        aB2 = f2fma(wb.x, h2.x, aB2); aB2 = f2fma(wb.y, h2.y, aB2);        \
        aB3 = f2fma(wb.x, h3.x, aB3); aB3 = f2fma(wb.y, h3.y, aB3);        \
    } while (0)

template<bool WRITE_Y>
__global__ void __launch_bounds__(NT, 1) scan_kernel(
    const float* __restrict__ xg, const float* __restrict__ wt4,
    const float* __restrict__ bhh, float* __restrict__ y, float* __restrict__ hout)
{
    extern __shared__ ulonglong2 Wsu[];              // [KCQ][G3] quads: (k01,k23) packed pairs
    __shared__ __align__(16) float hs[4][HH];        // per-batch hidden state
    __shared__ ulonglong2 gsum[G3];                  // per gate-col: (b0,b1),(b2,b3)

    const int tid = threadIdx.x;
    const int ca = tid;                              // column A: 0..383  (r all, z lower half)
    const int cb = tid + NT;                         // column B: 384..767 (z upper half, n)
    const bool b_has_x = (cb < 2 * HH);              // z columns take x in the dot fold
    const int bb0 = blockIdx.x * 4;

    const ulonglong2* __restrict__ wt4u = (const ulonglong2*)wt4;   // [HHQ][G3]

    // fill smem W cache
    for (int i = tid; i < KCQ * G3; i += NT)
        Wsu[i] = wt4u[i];

    // register-cached quads for this thread's two columns
    ulonglong2 wra[KRQ], wrb[KRQ];
    #pragma unroll
    for (int q = 0; q < KRQ; ++q) {
        wra[q] = wt4u[(size_t)(KCQ + q) * G3 + ca];
        wrb[q] = wt4u[(size_t)(KCQ + q) * G3 + cb];
    }

    const float biasa = bhh[ca];
    const float biasb = bhh[cb];
    if (tid < HH) { hs[0][tid] = 0.f; hs[1][tid] = 0.f; hs[2][tid] = 0.f; hs[3][tid] = 0.f; }
    __syncthreads();

    const size_t STRB  = (size_t)TT * G3;
    const size_t STRBY = (size_t)TT * HH;
    const float* xbase = xg + (size_t)bb0 * STRB;

    const ulonglong2* hq0 = (const ulonglong2*)hs[0];
    const ulonglong2* hq1 = (const ulonglong2*)hs[1];
    const ulonglong2* hq2 = (const ulonglong2*)hs[2];
    const ulonglong2* hq3 = (const ulonglong2*)hs[3];

    for (int t = 0; t < TT; ++t) {
        // --- prefetch x terms for this step ---
        const size_t tofs = (size_t)t * G3;
        float xa0, xa1, xa2, xa3;                     // col A always has x (ca < 512)
        {
            const float* p = xbase + tofs + ca;
            xa0 = p[0]; xa1 = p[STRB]; xa2 = p[2*STRB]; xa3 = p[3*STRB];
        }
        float xb0 = 0.f, xb1 = 0.f, xb2 = 0.f, xb3 = 0.f;
        if (b_has_x) {
            const float* p = xbase + tofs + cb;
            xb0 = p[0]; xb1 = p[STRB]; xb2 = p[2*STRB]; xb3 = p[3*STRB];
        }
        float xn0 = 0.f, xn1 = 0.f, xn2 = 0.f, xn3 = 0.f;
        if (tid < HH) {
            const float* p = xbase + tofs + 2 * HH + tid;
            xn0 = p[0]; xn1 = p[STRB]; xn2 = p[2*STRB]; xn3 = p[3*STRB];
        }

        u64 aA0=0, aA1=0, aA2=0, aA3=0;   // col A, batches 0..3 (k-pair split in lanes)
        u64 aB0=0, aB1=0, aB2=0, aB3=0;   // col B

        // smem segment
        #pragma unroll
        for (int q = 0; q < KCQ; ++q) {
            ulonglong2 wa = Wsu[q * G3 + ca];
            ulonglong2 wb = Wsu[q * G3 + cb];
            ulonglong2 h0 = hq0[q], h1 = hq1[q], h2 = hq2[q], h3 = hq3[q];
            QUAD_FMA(wa, wb, h0, h1, h2, h3);
        }
        // register segment
        #pragma unroll
        for (int q = 0; q < KRQ; ++q) {
            const int kq = KCQ + q;
            ulonglong2 h0 = hq0[kq], h1 = hq1[kq], h2 = hq2[kq], h3 = hq3[kq];
            QUAD_FMA(wra[q], wrb[q], h0, h1, h2, h3);
        }
        // streamed segment (L2-resident, coalesced)
        #pragma unroll
        for (int q = KSQ0; q < HHQ; ++q) {
            ulonglong2 wa = wt4u[(size_t)q * G3 + ca];
            ulonglong2 wb = wt4u[(size_t)q * G3 + cb];
            ulonglong2 h0 = hq0[q], h1 = hq1[q], h2 = hq2[q], h3 = hq3[q];
            QUAD_FMA(wa, wb, h0, h1, h2, h3);
        }

        // fold lo+hi, add bias (+x for r/z), publish
        {
            float2 f0 = unpk(aA0), f1 = unpk(aA1), f2 = unpk(aA2), f3 = unpk(aA3);
            float s0 = f0.x + f0.y + xa0 + biasa;
            float s1 = f1.x + f1.y + xa1 + biasa;
            float s2 = f2.x + f2.y + xa2 + biasa;
            float s3 = f3.x + f3.y + xa3 + biasa;
            gsum[ca] = make_ulonglong2(pk2(s0, s1), pk2(s2, s3));
        }
        {
            float2 f0 = unpk(aB0), f1 = unpk(aB1), f2 = unpk(aB2), f3 = unpk(aB3);
            float s0 = f0.x + f0.y + xb0 + biasb;
            float s1 = f1.x + f1.y + xb1 + biasb;
            float s2 = f2.x + f2.y + xb2 + biasb;
            float s3 = f3.x + f3.y + xb3 + biasb;
            gsum[cb] = make_ulonglong2(pk2(s0, s1), pk2(s2, s3));
        }
        __syncthreads();

        // --- combine (first 256 threads: unit j = tid) ---
        if (tid < HH) {
            ulonglong2 Rv = gsum[tid];
            ulonglong2 Zv = gsum[HH + tid];
            ulonglong2 Nv = gsum[2 * HH + tid];
            float2 ra = unpk(Rv.x), rb = unpk(Rv.y);
            float2 za = unpk(Zv.x), zb = unpk(Zv.y);
            float2 na = unpk(Nv.x), nb = unpk(Nv.y);
            float hr[4] = {ra.x, ra.y, rb.x, rb.y};
            float hz[4] = {za.x, za.y, zb.x, zb.y};
            float hn[4] = {na.x, na.y, nb.x, nb.y};
            float xn[4] = {xn0, xn1, xn2, xn3};
            float hnew[4];
            #pragma unroll
            for (int b = 0; b < 4; ++b) {
                const float r = sigmf(hr[b]);
                const float z = sigmf(hz[b]);
                const float n = tanh_fast(xn[b] + r * hn[b]);
                hnew[b] = (1.0f - z) * n + z * hs[b][tid];
                hs[b][tid] = hnew[b];
            }
            if (WRITE_Y) {
                float* yp = y + (size_t)bb0 * STRBY + (size_t)t * HH + tid;
                yp[0] = hnew[0]; yp[STRBY] = hnew[1];
                yp[2*STRBY] = hnew[2]; yp[3*STRBY] = hnew[3];
            }
        }
        __syncthreads();
    }

    if (!WRITE_Y && tid < HH) {
        hout[(size_t)(bb0 + 0) * HH + tid] = hs[0][tid];
        hout[(size_t)(bb0 + 1) * HH + tid] = hs[1][tid];
        hout[(size_t)(bb0 + 2) * HH + tid] = hs[2][tid];
        hout[(size_t)(bb0 + 3) * HH + tid] = hs[3][tid];
    }
}

// =====================================================================
// launch
// =====================================================================
extern "C" void kernel_launch(void* const* d_in, const int* in_sizes, int n_in,
                              void* d_out, int out_size)
{
    const float* obs   = (const float*)d_in[0];
    const float* w_ih0 = (const float*)d_in[1];
    const float* w_hh0 = (const float*)d_in[2];
    const float* b_ih0 = (const float*)d_in[3];
    const float* b_hh0 = (const float*)d_in[4];
    const float* w_ih1 = (const float*)d_in[5];
    const float* w_hh1 = (const float*)d_in[6];
    const float* b_ih1 = (const float*)d_in[7];
    const float* b_hh1 = (const float*)d_in[8];
    float* out = (float*)d_out;

    void* xg_p = nullptr; cudaGetSymbolAddress(&xg_p, g_xg);
    void* y0_p = nullptr; cudaGetSymbolAddress(&y0_p, g_y0);
    void* wt_p = nullptr; cudaGetSymbolAddress(&wt_p, g_wt);
    float* xg = (float*)xg_p;
    float* y0 = (float*)y0_p;
    float* wt = (float*)wt_p;

    cudaFuncSetAttribute(scan_kernel<true>,  cudaFuncAttributeMaxDynamicSharedMemorySize, SCAN_DSMEM);
    cudaFuncSetAttribute(scan_kernel<false>, cudaFuncAttributeMaxDynamicSharedMemorySize, SCAN_DSMEM);

    const int M = BB * TT;                 // 131072
    dim3 pgrid(G3 / PBN, M / PBM);         // (12, 1024)

    // layer 0
    transpose_whh<<<G3, HH>>>(w_hh0, wt);
    proj_kernel<<<pgrid, 256>>>(obs, w_ih0, b_ih0, xg, OBS);
    scan_kernel<true><<<BB / 4, NT, SCAN_DSMEM>>>(xg, wt, b_hh0, y0, nullptr);
    // layer 1
    transpose_whh<<<G3, HH>>>(w_hh1, wt);
    proj_kernel<<<pgrid, 256>>>(y0, w_ih1, b_ih1, xg, HH);
    scan_kernel<false><<<BB / 4, NT, SCAN_DSMEM>>>(xg, wt, b_hh1, nullptr, out);
}

// round 5
// speedup vs baseline: 1.0322x; 1.0322x over previous
#include <cuda_runtime.h>
#include <cstdint>
#include <cstddef>

// Problem dims
#define BB   256      // batch
#define TT   512      // time
#define OBS  64
#define HH   256      // hidden
#define G3   768      // 3*H
#define HHQ  64       // HH/4 (k-quads)

typedef unsigned long long u64;

// ---------------- scratch (device globals: allocation-free) ----------------
__device__ float g_xg[(size_t)BB * TT * G3];      // 402 MB: gate pre-activations
__device__ float g_y0[(size_t)BB * TT * HH];      // 134 MB: layer-0 outputs
__device__ float g_wt[2][(size_t)HH * G3];        // 2x786 KB: transposed W_hh per layer

// ---------------- f32x2 packed-fp32 helpers (sm_100+) ----------------
__device__ __forceinline__ u64 dupf(float a) {
    u64 r; asm("mov.b64 %0, {%1,%1};" : "=l"(r) : "f"(a)); return r;
}
__device__ __forceinline__ u64 pk2(float lo, float hi) {
    u64 r; asm("mov.b64 %0, {%1,%2};" : "=l"(r) : "f"(lo), "f"(hi)); return r;
}
__device__ __forceinline__ float2 unpk(u64 v) {
    float2 f; asm("mov.b64 {%0,%1}, %2;" : "=f"(f.x), "=f"(f.y) : "l"(v)); return f;
}
__device__ __forceinline__ u64 f2fma(u64 a, u64 b, u64 c) {
    u64 d; asm("fma.rn.f32x2 %0, %1, %2, %3;" : "=l"(d) : "l"(a), "l"(b), "l"(c)); return d;
}
__device__ __forceinline__ float sigmf(float x) {
    return 1.0f / (1.0f + __expf(-x));
}
__device__ __forceinline__ float tanh_fast(float x) {
    return 1.0f - __fdividef(2.0f, __expf(2.0f * x) + 1.0f);
}

// =====================================================================
// W_hh transpose: Whh[g][k] -> Wt4 quad-major:
//   Wt4[(k>>2)*G3*4 + g*4 + (k&3)]  (ulonglong2 view: wt4u[k/4][g])
// =====================================================================
__global__ void transpose_whh(const float* __restrict__ W, float* __restrict__ Wt4)
{
    const int g = blockIdx.x;        // 0..767
    const int k = threadIdx.x;       // 0..255
    const float v = W[(size_t)g * HH + k];   // coalesced read
    Wt4[(size_t)(k >> 2) * (G3 * 4) + g * 4 + (k & 3)] = v;
}

// =====================================================================
// Projection GEMM: C[M][768] = A[M][K] @ W[768][K]^T + bias[768]
// =====================================================================
#define PBM 128
#define PBN 64
#define PBK 16

__global__ void __launch_bounds__(256) proj_kernel(
    const float* __restrict__ A, const float* __restrict__ Wt,
    const float* __restrict__ bias, float* __restrict__ C, int K)
{
    __shared__ float As[2][PBK][PBM];
    __shared__ float Wsf[2][PBK][PBN];

    const int tid = threadIdx.x;
    const int tx = tid & 15;
    const int ty = tid >> 4;
    const int m0 = blockIdx.y * PBM;
    const int n0 = blockIdx.x * PBN;

    const int lrow = tid >> 2;
    const int lk4  = (tid & 3) << 2;
    const float* Ag0 = A  + (size_t)(m0 + lrow)      * K + lk4;
    const float* Ag1 = A  + (size_t)(m0 + lrow + 64) * K + lk4;
    const float* Wg  = Wt + (size_t)(n0 + lrow)      * K + lk4;

    u64 acc[8][2];
    #pragma unroll
    for (int i = 0; i < 8; ++i) { acc[i][0] = 0ULL; acc[i][1] = 0ULL; }

    const int panels = K >> 4;
    {
        float4 va0 = *(const float4*)(Ag0);
        float4 va1 = *(const float4*)(Ag1);
        float4 vw  = *(const float4*)(Wg);
        As[0][lk4+0][lrow] = va0.x; As[0][lk4+1][lrow] = va0.y;
        As[0][lk4+2][lrow] = va0.z; As[0][lk4+3][lrow] = va0.w;
        As[0][lk4+0][lrow+64] = va1.x; As[0][lk4+1][lrow+64] = va1.y;
        As[0][lk4+2][lrow+64] = va1.z; As[0][lk4+3][lrow+64] = va1.w;
        Wsf[0][lk4+0][lrow] = vw.x; Wsf[0][lk4+1][lrow] = vw.y;
        Wsf[0][lk4+2][lrow] = vw.z; Wsf[0][lk4+3][lrow] = vw.w;
    }
    __syncthreads();

    for (int p = 0; p < panels; ++p) {
        const int buf = p & 1;
        float4 na0, na1, nw;
        const bool more = (p + 1 < panels);
        if (more) {
            const int k0 = (p + 1) << 4;
            na0 = *(const float4*)(Ag0 + k0);
            na1 = *(const float4*)(Ag1 + k0);
            nw  = *(const float4*)(Wg  + k0);
        }
        #pragma unroll
        for (int k = 0; k < PBK; ++k) {
            float4 a0 = *(const float4*)&As[buf][k][ty * 8];
            float4 a1 = *(const float4*)&As[buf][k][ty * 8 + 4];
            ulonglong2 w = *(const ulonglong2*)&Wsf[buf][k][tx * 4];
            u64 d;
            d = dupf(a0.x); acc[0][0]=f2fma(d,w.x,acc[0][0]); acc[0][1]=f2fma(d,w.y,acc[0][1]);
            d = dupf(a0.y); acc[1][0]=f2fma(d,w.x,acc[1][0]); acc[1][1]=f2fma(d,w.y,acc[1][1]);
            d = dupf(a0.z); acc[2][0]=f2fma(d,w.x,acc[2][0]); acc[2][1]=f2fma(d,w.y,acc[2][1]);
            d = dupf(a0.w); acc[3][0]=f2fma(d,w.x,acc[3][0]); acc[3][1]=f2fma(d,w.y,acc[3][1]);
            d = dupf(a1.x); acc[4][0]=f2fma(d,w.x,acc[4][0]); acc[4][1]=f2fma(d,w.y,acc[4][1]);
            d = dupf(a1.y); acc[5][0]=f2fma(d,w.x,acc[5][0]); acc[5][1]=f2fma(d,w.y,acc[5][1]);
            d = dupf(a1.z); acc[6][0]=f2fma(d,w.x,acc[6][0]); acc[6][1]=f2fma(d,w.y,acc[6][1]);
            d = dupf(a1.w); acc[7][0]=f2fma(d,w.x,acc[7][0]); acc[7][1]=f2fma(d,w.y,acc[7][1]);
        }
        if (more) {
            const int nb = buf ^ 1;
            As[nb][lk4+0][lrow] = na0.x; As[nb][lk4+1][lrow] = na0.y;
            As[nb][lk4+2][lrow] = na0.z; As[nb][lk4+3][lrow] = na0.w;
            As[nb][lk4+0][lrow+64] = na1.x; As[nb][lk4+1][lrow+64] = na1.y;
            As[nb][lk4+2][lrow+64] = na1.z; As[nb][lk4+3][lrow+64] = na1.w;
            Wsf[nb][lk4+0][lrow] = nw.x; Wsf[nb][lk4+1][lrow] = nw.y;
            Wsf[nb][lk4+2][lrow] = nw.z; Wsf[nb][lk4+3][lrow] = nw.w;
        }
        __syncthreads();
    }

    const float4 bv = *(const float4*)&bias[n0 + tx * 4];
    #pragma unroll
    for (int i = 0; i < 8; ++i) {
        float2 v0 = unpk(acc[i][0]);
        float2 v1 = unpk(acc[i][1]);
        float4 o;
        o.x = v0.x + bv.x; o.y = v0.y + bv.y;
        o.z = v1.x + bv.z; o.w = v1.y + bv.w;
        const int m = m0 + ty * 8 + i;
        *(float4*)&C[(size_t)m * G3 + n0 + tx * 4] = o;
    }
}

// =====================================================================
// Recurrent scan v4 — "batch-per-lane", wavefront-minimal.
// 64 blocks x 768 threads (24 warps). Lane = (g = lane>>2, b = lane&3).
// Warp owns 32 cols [32*warp, 32*warp+32); thread computes cols
// c0, c0+8, c0+16, c0+24 (c0 = 32*warp + g) for its single batch b.
//  - weight access per (quad,i): 8 lanes x 16B contiguous, x4 batch
//    broadcast = one 128B line = 1 wavefront, zero redundancy.
//  - h access per quad: 4 distinct 16B rows (bank-staggered) with 8-way
//    broadcast = 1 wavefront, value reused across 4 columns.
//  - gsum[col][b]: STS.32 addr = 4*lane -> fully coalesced.
// W residency: quads [0,16) in smem (196.6KB), [16,64) streamed from L2.
// =====================================================================
#define KCQ4 16
#define SCAN4_DSMEM (KCQ4 * G3 * 16)     // 196608 B
#define HPAD 264                          // h row stride (floats): 1056B, 16B-aligned, bank-staggered

template<bool WRITE_Y>
__global__ void __launch_bounds__(768, 1) scan_kernel(
    const float* __restrict__ xg, const float* __restrict__ wt4,
    const float* __restrict__ bhh, float* __restrict__ y, float* __restrict__ hout)
{
    extern __shared__ ulonglong2 Wsu[];              // [KCQ4][G3]
    __shared__ __align__(16) float hs[4][HPAD];      // hidden state, per batch row
    __shared__ __align__(16) float gsum[G3][4];      // dot results [col][batch]

    const int tid  = threadIdx.x;
    const int lane = tid & 31;
    const int warp = tid >> 5;
    const int g    = lane >> 2;          // col-group 0..7
    const int b    = lane & 3;           // batch 0..3
    const int c0   = warp * 32 + g;      // cols: c0 + 8*i, i = 0..3
    const int bb0  = blockIdx.x * 4;

    const ulonglong2* __restrict__ wt4u = (const ulonglong2*)wt4;   // [HHQ][G3]

    // fill smem W cache (coalesced 16B copy)
    for (int i = tid; i < KCQ4 * G3; i += 768)
        Wsu[i] = wt4u[i];

    // zero h
    for (int i = tid; i < 4 * HPAD; i += 768)
        ((float*)hs)[i] = 0.f;

    // combine-thread constants
    float br = 0.f, bz = 0.f, bn = 0.f;
    if (tid < HH) {
        br = bhh[tid]; bz = bhh[HH + tid]; bn = bhh[2 * HH + tid];
    }
    __syncthreads();

    const size_t STRB  = (size_t)TT * G3;
    const size_t STRBY = (size_t)TT * HH;
    const float* xbase = xg + (size_t)bb0 * STRB;

    const ulonglong2* __restrict__ hrow = (const ulonglong2*)hs[b];  // this lane's batch row

    for (int t = 0; t < TT; ++t) {
        // ---- x prefetch (combine threads only; consumed after the dot) ----
        float xr[4], xz[4], xn[4];
        if (tid < HH) {
            const size_t tofs = (size_t)t * G3;
            #pragma unroll
            for (int bb = 0; bb < 4; ++bb) {
                const float* p = xbase + (size_t)bb * STRB + tofs;
                xr[bb] = p[tid];
                xz[bb] = p[HH + tid];
                xn[bb] = p[2 * HH + tid];
            }
        }

        // ---- dot: 4 columns x 1 batch x 256 k ----
        u64 a0 = 0, a1 = 0, a2 = 0, a3 = 0;

        #pragma unroll
        for (int q = 0; q < KCQ4; ++q) {             // smem-cached quads
            ulonglong2 h = hrow[q];                  // 1 wf (bank-staggered 4-addr bcast)
            ulonglong2 w0 = Wsu[q * G3 + c0];
            ulonglong2 w1 = Wsu[q * G3 + c0 + 8];
            ulonglong2 w2 = Wsu[q * G3 + c0 + 16];
            ulonglong2 w3 = Wsu[q * G3 + c0 + 24];
            a0 = f2fma(w0.x, h.x, a0); a0 = f2fma(w0.y, h.y, a0);
            a1 = f2fma(w1.x, h.x, a1); a1 = f2fma(w1.y, h.y, a1);
            a2 = f2fma(w2.x, h.x, a2); a2 = f2fma(w2.y, h.y, a2);
            a3 = f2fma(w3.x, h.x, a3); a3 = f2fma(w3.y, h.y, a3);
        }
        #pragma unroll 4
        for (int q = KCQ4; q < HHQ; ++q) {           // streamed quads (L2, 1 line/instr)
            const ulonglong2* wp = wt4u + (size_t)q * G3;
            ulonglong2 w0 = wp[c0];
            ulonglong2 w1 = wp[c0 + 8];
            ulonglong2 w2 = wp[c0 + 16];
            ulonglong2 w3 = wp[c0 + 24];
            ulonglong2 h = hrow[q];
            a0 = f2fma(w0.x, h.x, a0); a0 = f2fma(w0.y, h.y, a0);
            a1 = f2fma(w1.x, h.x, a1); a1 = f2fma(w1.y, h.y, a1);
            a2 = f2fma(w2.x, h.x, a2); a2 = f2fma(w2.y, h.y, a2);
            a3 = f2fma(w3.x, h.x, a3); a3 = f2fma(w3.y, h.y, a3);
        }

        // fold k-pair lanes, publish (coalesced STS.32: addr = 4*lane)
        { float2 f = unpk(a0); gsum[c0     ][b] = f.x + f.y; }
        { float2 f = unpk(a1); gsum[c0 +  8][b] = f.x + f.y; }
        { float2 f = unpk(a2); gsum[c0 + 16][b] = f.x + f.y; }
        { float2 f = unpk(a3); gsum[c0 + 24][b] = f.x + f.y; }
        __syncthreads();

        // ---- combine (threads 0..255, unit j = tid) ----
        if (tid < HH) {
            float4 R = *(const float4*)gsum[tid];
            float4 Z = *(const float4*)gsum[HH + tid];
            float4 N = *(const float4*)gsum[2 * HH + tid];
            float hrv[4] = {R.x, R.y, R.z, R.w};
            float hzv[4] = {Z.x, Z.y, Z.z, Z.w};
            float hnv[4] = {N.x, N.y, N.z, N.w};
            float hnew[4];
            #pragma unroll
            for (int bb = 0; bb < 4; ++bb) {
                const float r = sigmf(xr[bb] + hrv[bb] + br);
                const float z = sigmf(xz[bb] + hzv[bb] + bz);
                const float n = tanh_fast(xn[bb] + r * (hnv[bb] + bn));
                hnew[bb] = (1.0f - z) * n + z * hs[bb][tid];
                hs[bb][tid] = hnew[bb];
            }
            if (WRITE_Y) {
                float* yp = y + (size_t)bb0 * STRBY + (size_t)t * HH + tid;
                yp[0] = hnew[0]; yp[STRBY] = hnew[1];
                yp[2 * STRBY] = hnew[2]; yp[3 * STRBY] = hnew[3];
            }
        }
        __syncthreads();
    }

    if (!WRITE_Y && tid < HH) {
        hout[(size_t)(bb0 + 0) * HH + tid] = hs[0][tid];
        hout[(size_t)(bb0 + 1) * HH + tid] = hs[1][tid];
        hout[(size_t)(bb0 + 2) * HH + tid] = hs[2][tid];
        hout[(size_t)(bb0 + 3) * HH + tid] = hs[3][tid];
    }
}

// =====================================================================
// launch
// =====================================================================
extern "C" void kernel_launch(void* const* d_in, const int* in_sizes, int n_in,
                              void* d_out, int out_size)
{
    const float* obs   = (const float*)d_in[0];
    const float* w_ih0 = (const float*)d_in[1];
    const float* w_hh0 = (const float*)d_in[2];
    const float* b_ih0 = (const float*)d_in[3];
    const float* b_hh0 = (const float*)d_in[4];
    const float* w_ih1 = (const float*)d_in[5];
    const float* w_hh1 = (const float*)d_in[6];
    const float* b_ih1 = (const float*)d_in[7];
    const float* b_hh1 = (const float*)d_in[8];
    float* out = (float*)d_out;

    void* xg_p = nullptr; cudaGetSymbolAddress(&xg_p, g_xg);
    void* y0_p = nullptr; cudaGetSymbolAddress(&y0_p, g_y0);
    void* wt_p = nullptr; cudaGetSymbolAddress(&wt_p, g_wt);
    float* xg  = (float*)xg_p;
    float* y0  = (float*)y0_p;
    float* wt0 = (float*)wt_p;
    float* wt1 = wt0 + (size_t)HH * G3;

    cudaFuncSetAttribute(scan_kernel<true>,  cudaFuncAttributeMaxDynamicSharedMemorySize, SCAN4_DSMEM);
    cudaFuncSetAttribute(scan_kernel<false>, cudaFuncAttributeMaxDynamicSharedMemorySize, SCAN4_DSMEM);

    const int M = BB * TT;                 // 131072
    dim3 pgrid(G3 / PBN, M / PBM);         // (12, 1024)

    // transposes first (also pushes heavy kernels into the ncu capture window)
    transpose_whh<<<G3, HH>>>(w_hh0, wt0);
    transpose_whh<<<G3, HH>>>(w_hh1, wt1);

    // layer 0
    proj_kernel<<<pgrid, 256>>>(obs, w_ih0, b_ih0, xg, OBS);
    scan_kernel<true><<<BB / 4, 768, SCAN4_DSMEM>>>(xg, wt0, b_hh0, y0, nullptr);
    // layer 1
    proj_kernel<<<pgrid, 256>>>(y0, w_ih1, b_ih1, xg, HH);
    scan_kernel<false><<<BB / 4, 768, SCAN4_DSMEM>>>(xg, wt1, b_hh1, nullptr, out);
}

// round 6
// speedup vs baseline: 1.0324x; 1.0002x over previous
#include <cuda_runtime.h>
#include <cstdint>
#include <cstddef>

// Problem dims
#define BB   256      // batch
#define TT   512      // time
#define OBS  64
#define HH   256      // hidden
#define G3   768      // 3*H
#define HHQ  64       // HH/4 (k-quads)

typedef unsigned long long u64;

// ---------------- scratch (device globals: allocation-free) ----------------
__device__ float g_xg[(size_t)BB * TT * G3];      // 402 MB: gate pre-activations
__device__ float g_y0[(size_t)BB * TT * HH];      // 134 MB: layer-0 outputs
__device__ float g_wt[2][(size_t)HH * G3];        // 2x786 KB: transposed W_hh per layer

// ---------------- f32x2 packed-fp32 helpers (sm_100+) ----------------
__device__ __forceinline__ u64 dupf(float a) {
    u64 r; asm("mov.b64 %0, {%1,%1};" : "=l"(r) : "f"(a)); return r;
}
__device__ __forceinline__ u64 pk2(float lo, float hi) {
    u64 r; asm("mov.b64 %0, {%1,%2};" : "=l"(r) : "f"(lo), "f"(hi)); return r;
}
__device__ __forceinline__ float2 unpk(u64 v) {
    float2 f; asm("mov.b64 {%0,%1}, %2;" : "=f"(f.x), "=f"(f.y) : "l"(v)); return f;
}
__device__ __forceinline__ u64 f2fma(u64 a, u64 b, u64 c) {
    u64 d; asm("fma.rn.f32x2 %0, %1, %2, %3;" : "=l"(d) : "l"(a), "l"(b), "l"(c)); return d;
}
__device__ __forceinline__ float sigmf(float x) {
    return 1.0f / (1.0f + __expf(-x));
}
__device__ __forceinline__ float tanh_fast(float x) {
    return 1.0f - __fdividef(2.0f, __expf(2.0f * x) + 1.0f);
}

// =====================================================================
// W_hh transpose: Whh[g][k] -> Wt4 quad-major:
//   Wt4[(k>>2)*G3*4 + g*4 + (k&3)]  (ulonglong2 view: wt4u[k/4][g])
// =====================================================================
__global__ void transpose_whh(const float* __restrict__ W, float* __restrict__ Wt4)
{
    const int g = blockIdx.x;        // 0..767
    const int k = threadIdx.x;       // 0..255
    const float v = W[(size_t)g * HH + k];   // coalesced read
    Wt4[(size_t)(k >> 2) * (G3 * 4) + g * 4 + (k & 3)] = v;
}

// =====================================================================
// Projection GEMM: C[M][768] = A[M][K] @ W[768][K]^T + bias[768]
// =====================================================================
#define PBM 128
#define PBN 64
#define PBK 16

__global__ void __launch_bounds__(256) proj_kernel(
    const float* __restrict__ A, const float* __restrict__ Wt,
    const float* __restrict__ bias, float* __restrict__ C, int K)
{
    __shared__ float As[2][PBK][PBM];
    __shared__ float Wsf[2][PBK][PBN];

    const int tid = threadIdx.x;
    const int tx = tid & 15;
    const int ty = tid >> 4;
    const int m0 = blockIdx.y * PBM;
    const int n0 = blockIdx.x * PBN;

    const int lrow = tid >> 2;
    const int lk4  = (tid & 3) << 2;
    const float* Ag0 = A  + (size_t)(m0 + lrow)      * K + lk4;
    const float* Ag1 = A  + (size_t)(m0 + lrow + 64) * K + lk4;
    const float* Wg  = Wt + (size_t)(n0 + lrow)      * K + lk4;

    u64 acc[8][2];
    #pragma unroll
    for (int i = 0; i < 8; ++i) { acc[i][0] = 0ULL; acc[i][1] = 0ULL; }

    const int panels = K >> 4;
    {
        float4 va0 = *(const float4*)(Ag0);
        float4 va1 = *(const float4*)(Ag1);
        float4 vw  = *(const float4*)(Wg);
        As[0][lk4+0][lrow] = va0.x; As[0][lk4+1][lrow] = va0.y;
        As[0][lk4+2][lrow] = va0.z; As[0][lk4+3][lrow] = va0.w;
        As[0][lk4+0][lrow+64] = va1.x; As[0][lk4+1][lrow+64] = va1.y;
        As[0][lk4+2][lrow+64] = va1.z; As[0][lk4+3][lrow+64] = va1.w;
        Wsf[0][lk4+0][lrow] = vw.x; Wsf[0][lk4+1][lrow] = vw.y;
        Wsf[0][lk4+2][lrow] = vw.z; Wsf[0][lk4+3][lrow] = vw.w;
    }
    __syncthreads();

    for (int p = 0; p < panels; ++p) {
        const int buf = p & 1;
        float4 na0, na1, nw;
        const bool more = (p + 1 < panels);
        if (more) {
            const int k0 = (p + 1) << 4;
            na0 = *(const float4*)(Ag0 + k0);
            na1 = *(const float4*)(Ag1 + k0);
            nw  = *(const float4*)(Wg  + k0);
        }
        #pragma unroll
        for (int k = 0; k < PBK; ++k) {
            float4 a0 = *(const float4*)&As[buf][k][ty * 8];
            float4 a1 = *(const float4*)&As[buf][k][ty * 8 + 4];
            ulonglong2 w = *(const ulonglong2*)&Wsf[buf][k][tx * 4];
            u64 d;
            d = dupf(a0.x); acc[0][0]=f2fma(d,w.x,acc[0][0]); acc[0][1]=f2fma(d,w.y,acc[0][1]);
            d = dupf(a0.y); acc[1][0]=f2fma(d,w.x,acc[1][0]); acc[1][1]=f2fma(d,w.y,acc[1][1]);
            d = dupf(a0.z); acc[2][0]=f2fma(d,w.x,acc[2][0]); acc[2][1]=f2fma(d,w.y,acc[2][1]);
            d = dupf(a0.w); acc[3][0]=f2fma(d,w.x,acc[3][0]); acc[3][1]=f2fma(d,w.y,acc[3][1]);
            d = dupf(a1.x); acc[4][0]=f2fma(d,w.x,acc[4][0]); acc[4][1]=f2fma(d,w.y,acc[4][1]);
            d = dupf(a1.y); acc[5][0]=f2fma(d,w.x,acc[5][0]); acc[5][1]=f2fma(d,w.y,acc[5][1]);
            d = dupf(a1.z); acc[6][0]=f2fma(d,w.x,acc[6][0]); acc[6][1]=f2fma(d,w.y,acc[6][1]);
            d = dupf(a1.w); acc[7][0]=f2fma(d,w.x,acc[7][0]); acc[7][1]=f2fma(d,w.y,acc[7][1]);
        }
        if (more) {
            const int nb = buf ^ 1;
            As[nb][lk4+0][lrow] = na0.x; As[nb][lk4+1][lrow] = na0.y;
            As[nb][lk4+2][lrow] = na0.z; As[nb][lk4+3][lrow] = na0.w;
            As[nb][lk4+0][lrow+64] = na1.x; As[nb][lk4+1][lrow+64] = na1.y;
            As[nb][lk4+2][lrow+64] = na1.z; As[nb][lk4+3][lrow+64] = na1.w;
            Wsf[nb][lk4+0][lrow] = nw.x; Wsf[nb][lk4+1][lrow] = nw.y;
            Wsf[nb][lk4+2][lrow] = nw.z; Wsf[nb][lk4+3][lrow] = nw.w;
        }
        __syncthreads();
    }

    const float4 bv = *(const float4*)&bias[n0 + tx * 4];
    #pragma unroll
    for (int i = 0; i < 8; ++i) {
        float2 v0 = unpk(acc[i][0]);
        float2 v1 = unpk(acc[i][1]);
        float4 o;
        o.x = v0.x + bv.x; o.y = v0.y + bv.y;
        o.z = v1.x + bv.z; o.w = v1.y + bv.w;
        const int m = m0 + ty * 8 + i;
        *(float4*)&C[(size_t)m * G3 + n0 + tx * 4] = o;
    }
}

// =====================================================================
// Recurrent scan v5 — batch-per-lane + smem x-staging + depth-2 LDG pipe.
// 64 blocks x 768 threads. Lane = (g = lane>>2, b = lane&3); thread does
// cols c0+8i (i<4) for batch b. W quads [0,KCQ5) in smem, rest streamed
// through an explicit double-buffered __ldg pipeline whose first load is
// issued before the smem-FMA segment (hides first L2 round trip).
// x gate pre-activations staged cooperatively into smem by all 24 warps.
// =====================================================================
#define KCQ5 15
#define SCAN5_DSMEM (KCQ5 * G3 * 16)     // 184320 B
#define HPAD 264                          // h row stride: bank-staggered

#define QFMA(wq, hq)                                            \
    do {                                                        \
        a0 = f2fma((wq##0).x, (hq).x, a0);                      \
        a0 = f2fma((wq##0).y, (hq).y, a0);                      \
        a1 = f2fma((wq##1).x, (hq).x, a1);                      \
        a1 = f2fma((wq##1).y, (hq).y, a1);                      \
        a2 = f2fma((wq##2).x, (hq).x, a2);                      \
        a2 = f2fma((wq##2).y, (hq).y, a2);                      \
        a3 = f2fma((wq##3).x, (hq).x, a3);                      \
        a3 = f2fma((wq##3).y, (hq).y, a3);                      \
    } while (0)

template<bool WRITE_Y>
__global__ void __launch_bounds__(768, 1) scan_kernel(
    const float* __restrict__ xg, const float* __restrict__ wt4,
    const float* __restrict__ bhh, float* __restrict__ y, float* __restrict__ hout)
{
    extern __shared__ ulonglong2 Wsu[];              // [KCQ5][G3]
    __shared__ __align__(16) float hs[4][HPAD];      // hidden state per batch row
    __shared__ __align__(16) float gsum[G3][4];      // dot results [col][batch]
    __shared__ __align__(16) float xstage[G3][4];    // staged x terms [gatecol][batch]

    const int tid  = threadIdx.x;
    const int lane = tid & 31;
    const int warp = tid >> 5;
    const int g    = lane >> 2;          // col-group 0..7
    const int b    = lane & 3;           // batch 0..3
    const int c0   = warp * 32 + g;      // cols: c0 + 8*i
    const int bb0  = blockIdx.x * 4;

    const ulonglong2* __restrict__ wt4u = (const ulonglong2*)wt4;

    // fill smem W cache
    for (int i = tid; i < KCQ5 * G3; i += 768)
        Wsu[i] = wt4u[i];

    // zero h
    for (int i = tid; i < 4 * HPAD; i += 768)
        ((float*)hs)[i] = 0.f;

    // combine-thread constants
    float br = 0.f, bz = 0.f, bn = 0.f;
    if (tid < HH) {
        br = bhh[tid]; bz = bhh[HH + tid]; bn = bhh[2 * HH + tid];
    }
    __syncthreads();

    const size_t STRB  = (size_t)TT * G3;
    const size_t STRBY = (size_t)TT * HH;
    // x staging: this thread loads gate-col xc = tid (0..767), all 4 batches
    const float* xcol = xg + (size_t)bb0 * STRB + tid;

    const ulonglong2* __restrict__ hrow = (const ulonglong2*)hs[b];

    for (int t = 0; t < TT; ++t) {
        const size_t tofs = (size_t)t * G3;

        // ---- (1) issue x loads for this step (all 24 warps, coalesced) ----
        float xv0 = xcol[tofs];
        float xv1 = xcol[STRB + tofs];
        float xv2 = xcol[2 * STRB + tofs];
        float xv3 = xcol[3 * STRB + tofs];

        // ---- (2) issue first streamed-W prefetch (hidden under smem seg) ----
        const ulonglong2* wp0 = wt4u + (size_t)KCQ5 * G3;
        ulonglong2 pA0 = __ldg(wp0 + c0);
        ulonglong2 pA1 = __ldg(wp0 + c0 + 8);
        ulonglong2 pA2 = __ldg(wp0 + c0 + 16);
        ulonglong2 pA3 = __ldg(wp0 + c0 + 24);

        u64 a0 = 0, a1 = 0, a2 = 0, a3 = 0;

        // ---- (3) smem-cached segment ----
        #pragma unroll
        for (int q = 0; q < KCQ5; ++q) {
            ulonglong2 h = hrow[q];
            ulonglong2 w0 = Wsu[q * G3 + c0];
            ulonglong2 w1 = Wsu[q * G3 + c0 + 8];
            ulonglong2 w2 = Wsu[q * G3 + c0 + 16];
            ulonglong2 w3 = Wsu[q * G3 + c0 + 24];
            QFMA(w, h);
        }

        // ---- (4) streamed segment: depth-2 double-buffered pipeline ----
        // quads KCQ5 .. 63 (49 quads). Buffer A holds quad q, B prefetches q+1.
        {
            ulonglong2 pB0, pB1, pB2, pB3;
            #pragma unroll
            for (int q = KCQ5; q < HHQ - 1; q += 2) {
                const ulonglong2* wpn = wt4u + (size_t)(q + 1) * G3;
                pB0 = __ldg(wpn + c0);
                pB1 = __ldg(wpn + c0 + 8);
                pB2 = __ldg(wpn + c0 + 16);
                pB3 = __ldg(wpn + c0 + 24);
                {
                    ulonglong2 h = hrow[q];
                    QFMA(pA, h);
                }
                if (q + 2 < HHQ) {
                    const ulonglong2* wpn2 = wt4u + (size_t)(q + 2) * G3;
                    pA0 = __ldg(wpn2 + c0);
                    pA1 = __ldg(wpn2 + c0 + 8);
                    pA2 = __ldg(wpn2 + c0 + 16);
                    pA3 = __ldg(wpn2 + c0 + 24);
                }
                {
                    ulonglong2 h = hrow[q + 1];
                    QFMA(pB, h);
                }
            }
            // KCQ5=15 -> 49 quads, loop covers 15..62, tail quad 63 in pA
            {
                ulonglong2 h = hrow[HHQ - 1];
                QFMA(pA, h);
            }
        }

        // ---- (5) stage x into smem (loads issued ~5K cyc ago) ----
        *(float4*)xstage[tid] = make_float4(xv0, xv1, xv2, xv3);

        // ---- (6) fold k-pair lanes, publish dots ----
        { float2 f = unpk(a0); gsum[c0     ][b] = f.x + f.y; }
        { float2 f = unpk(a1); gsum[c0 +  8][b] = f.x + f.y; }
        { float2 f = unpk(a2); gsum[c0 + 16][b] = f.x + f.y; }
        { float2 f = unpk(a3); gsum[c0 + 24][b] = f.x + f.y; }
        __syncthreads();

        // ---- (7) combine (threads 0..255, unit j = tid) ----
        if (tid < HH) {
            float4 R  = *(const float4*)gsum[tid];
            float4 Z  = *(const float4*)gsum[HH + tid];
            float4 N  = *(const float4*)gsum[2 * HH + tid];
            float4 XR = *(const float4*)xstage[tid];
            float4 XZ = *(const float4*)xstage[HH + tid];
            float4 XN = *(const float4*)xstage[2 * HH + tid];
            float hrv[4] = {R.x + XR.x, R.y + XR.y, R.z + XR.z, R.w + XR.w};
            float hzv[4] = {Z.x + XZ.x, Z.y + XZ.y, Z.z + XZ.z, Z.w + XZ.w};
            float hnv[4] = {N.x, N.y, N.z, N.w};
            float xnv[4] = {XN.x, XN.y, XN.z, XN.w};
            float hnew[4];
            #pragma unroll
            for (int bb = 0; bb < 4; ++bb) {
                const float r = sigmf(hrv[bb] + br);
                const float z = sigmf(hzv[bb] + bz);
                const float n = tanh_fast(xnv[bb] + r * (hnv[bb] + bn));
                hnew[bb] = (1.0f - z) * n + z * hs[bb][tid];
                hs[bb][tid] = hnew[bb];
            }
            if (WRITE_Y) {
                float* yp = y + (size_t)bb0 * STRBY + (size_t)t * HH + tid;
                yp[0] = hnew[0]; yp[STRBY] = hnew[1];
                yp[2 * STRBY] = hnew[2]; yp[3 * STRBY] = hnew[3];
            }
        }
        __syncthreads();
    }

    if (!WRITE_Y && tid < HH) {
        hout[(size_t)(bb0 + 0) * HH + tid] = hs[0][tid];
        hout[(size_t)(bb0 + 1) * HH + tid] = hs[1][tid];
        hout[(size_t)(bb0 + 2) * HH + tid] = hs[2][tid];
        hout[(size_t)(bb0 + 3) * HH + tid] = hs[3][tid];
    }
}

// =====================================================================
// launch
// =====================================================================
extern "C" void kernel_launch(void* const* d_in, const int* in_sizes, int n_in,
                              void* d_out, int out_size)
{
    const float* obs   = (const float*)d_in[0];
    const float* w_ih0 = (const float*)d_in[1];
    const float* w_hh0 = (const float*)d_in[2];
    const float* b_ih0 = (const float*)d_in[3];
    const float* b_hh0 = (const float*)d_in[4];
    const float* w_ih1 = (const float*)d_in[5];
    const float* w_hh1 = (const float*)d_in[6];
    const float* b_ih1 = (const float*)d_in[7];
    const float* b_hh1 = (const float*)d_in[8];
    float* out = (float*)d_out;

    void* xg_p = nullptr; cudaGetSymbolAddress(&xg_p, g_xg);
    void* y0_p = nullptr; cudaGetSymbolAddress(&y0_p, g_y0);
    void* wt_p = nullptr; cudaGetSymbolAddress(&wt_p, g_wt);
    float* xg  = (float*)xg_p;
    float* y0  = (float*)y0_p;
    float* wt0 = (float*)wt_p;
    float* wt1 = wt0 + (size_t)HH * G3;

    cudaFuncSetAttribute(scan_kernel<true>,  cudaFuncAttributeMaxDynamicSharedMemorySize, SCAN5_DSMEM);
    cudaFuncSetAttribute(scan_kernel<false>, cudaFuncAttributeMaxDynamicSharedMemorySize, SCAN5_DSMEM);

    const int M = BB * TT;                 // 131072
    dim3 pgrid(G3 / PBN, M / PBM);         // (12, 1024)

    transpose_whh<<<G3, HH>>>(w_hh0, wt0);
    transpose_whh<<<G3, HH>>>(w_hh1, wt1);

    // layer 0
    proj_kernel<<<pgrid, 256>>>(obs, w_ih0, b_ih0, xg, OBS);
    scan_kernel<true><<<BB / 4, 768, SCAN5_DSMEM>>>(xg, wt0, b_hh0, y0, nullptr);
    // layer 1
    proj_kernel<<<pgrid, 256>>>(y0, w_ih1, b_ih1, xg, HH);
    scan_kernel<false><<<BB / 4, 768, SCAN5_DSMEM>>>(xg, wt1, b_hh1, nullptr, out);
}

// round 7
// speedup vs baseline: 1.7781x; 1.7223x over previous
#include <cuda_runtime.h>
#include <cstdint>
#include <cstddef>

// Problem dims
#define BB   256      // batch
#define TT   512      // time
#define OBS  64
#define HH   256      // hidden
#define G3   768      // 3*H
#define HHQ  64       // HH/4 (k-quads)

// split-scan config
#define NTH  768      // threads per scan CTA
#define NCOL 384      // gate-cols per CTA (3 gates x 128 units)
#define KQ   30       // k-quads cached in smem; 64-KQ streamed from L2
#define HPD  264      // hidden-state row stride (floats), bank-staggered
#define SCAN_DSMEM (KQ * NCOL * 16)   // 184320 B

typedef unsigned long long u64;

// ---------------- scratch (device globals: allocation-free) ----------------
__device__ float g_xg[(size_t)BB * TT * G3];          // 402 MB gate pre-activations
__device__ float g_y0[(size_t)BB * TT * HH];          // 134 MB layer-0 outputs
__device__ float g_wth[2][2][(size_t)NCOL * HH];      // [layer][half] repacked W_hh
__device__ float g_mail[(size_t)64 * TT * 2 * 512];   // h exchange mailboxes (134 MB)
__device__ int   g_flag[(size_t)64 * TT * 2];         // per-step flags

// ---------------- f32x2 packed-fp32 helpers (sm_100+) ----------------
__device__ __forceinline__ u64 dupf(float a) {
    u64 r; asm("mov.b64 %0, {%1,%1};" : "=l"(r) : "f"(a)); return r;
}
__device__ __forceinline__ float2 unpk(u64 v) {
    float2 f; asm("mov.b64 {%0,%1}, %2;" : "=f"(f.x), "=f"(f.y) : "l"(v)); return f;
}
__device__ __forceinline__ u64 f2fma(u64 a, u64 b, u64 c) {
    u64 d; asm("fma.rn.f32x2 %0, %1, %2, %3;" : "=l"(d) : "l"(a), "l"(b), "l"(c)); return d;
}
__device__ __forceinline__ float sigmf(float x) {
    return 1.0f / (1.0f + __expf(-x));
}
__device__ __forceinline__ float tanh_fast(float x) {
    return 1.0f - __fdividef(2.0f, __expf(2.0f * x) + 1.0f);
}

// =====================================================================
// W_hh repack into per-half, quad-major layout:
//   half p owns units j with (j>>7)==p; local col c = gate*128 + (j&127)
//   wth[p][(k>>2)*NCOL*4 + c*4 + (k&3)]   (ulonglong2 view: [quad][c])
// =====================================================================
__global__ void repack_whh(const float* __restrict__ W,
                           float* __restrict__ WA, float* __restrict__ WB)
{
    const int gRow = blockIdx.x;      // 0..767
    const int k    = threadIdx.x;     // 0..255
    const float v  = W[(size_t)gRow * HH + k];
    const int gate = gRow >> 8;
    const int j    = gRow & 255;
    const int p    = j >> 7;
    const int c    = gate * 128 + (j & 127);
    float* out = p ? WB : WA;
    out[(size_t)(k >> 2) * (NCOL * 4) + c * 4 + (k & 3)] = v;
}

// flag reset (runs before each scan)
__global__ void reset_flags(int* __restrict__ f)
{
    f[blockIdx.x * 1024 + threadIdx.x] = 0;
}

// =====================================================================
// Projection GEMM: C[M][768] = A[M][K] @ W[768][K]^T + bias[768]
// =====================================================================
#define PBM 128
#define PBN 64
#define PBK 16

__global__ void __launch_bounds__(256) proj_kernel(
    const float* __restrict__ A, const float* __restrict__ Wt,
    const float* __restrict__ bias, float* __restrict__ C, int K)
{
    __shared__ float As[2][PBK][PBM];
    __shared__ float Wsf[2][PBK][PBN];

    const int tid = threadIdx.x;
    const int tx = tid & 15;
    const int ty = tid >> 4;
    const int m0 = blockIdx.y * PBM;
    const int n0 = blockIdx.x * PBN;

    const int lrow = tid >> 2;
    const int lk4  = (tid & 3) << 2;
    const float* Ag0 = A  + (size_t)(m0 + lrow)      * K + lk4;
    const float* Ag1 = A  + (size_t)(m0 + lrow + 64) * K + lk4;
    const float* Wg  = Wt + (size_t)(n0 + lrow)      * K + lk4;

    u64 acc[8][2];
    #pragma unroll
    for (int i = 0; i < 8; ++i) { acc[i][0] = 0ULL; acc[i][1] = 0ULL; }

    const int panels = K >> 4;
    {
        float4 va0 = *(const float4*)(Ag0);
        float4 va1 = *(const float4*)(Ag1);
        float4 vw  = *(const float4*)(Wg);
        As[0][lk4+0][lrow] = va0.x; As[0][lk4+1][lrow] = va0.y;
        As[0][lk4+2][lrow] = va0.z; As[0][lk4+3][lrow] = va0.w;
        As[0][lk4+0][lrow+64] = va1.x; As[0][lk4+1][lrow+64] = va1.y;
        As[0][lk4+2][lrow+64] = va1.z; As[0][lk4+3][lrow+64] = va1.w;
        Wsf[0][lk4+0][lrow] = vw.x; Wsf[0][lk4+1][lrow] = vw.y;
        Wsf[0][lk4+2][lrow] = vw.z; Wsf[0][lk4+3][lrow] = vw.w;
    }
    __syncthreads();

    for (int p = 0; p < panels; ++p) {
        const int buf = p & 1;
        float4 na0, na1, nw;
        const bool more = (p + 1 < panels);
        if (more) {
            const int k0 = (p + 1) << 4;
            na0 = *(const float4*)(Ag0 + k0);
            na1 = *(const float4*)(Ag1 + k0);
            nw  = *(const float4*)(Wg  + k0);
        }
        #pragma unroll
        for (int k = 0; k < PBK; ++k) {
            float4 a0 = *(const float4*)&As[buf][k][ty * 8];
            float4 a1 = *(const float4*)&As[buf][k][ty * 8 + 4];
            ulonglong2 w = *(const ulonglong2*)&Wsf[buf][k][tx * 4];
            u64 d;
            d = dupf(a0.x); acc[0][0]=f2fma(d,w.x,acc[0][0]); acc[0][1]=f2fma(d,w.y,acc[0][1]);
            d = dupf(a0.y); acc[1][0]=f2fma(d,w.x,acc[1][0]); acc[1][1]=f2fma(d,w.y,acc[1][1]);
            d = dupf(a0.z); acc[2][0]=f2fma(d,w.x,acc[2][0]); acc[2][1]=f2fma(d,w.y,acc[2][1]);
            d = dupf(a0.w); acc[3][0]=f2fma(d,w.x,acc[3][0]); acc[3][1]=f2fma(d,w.y,acc[3][1]);
            d = dupf(a1.x); acc[4][0]=f2fma(d,w.x,acc[4][0]); acc[4][1]=f2fma(d,w.y,acc[4][1]);
            d = dupf(a1.y); acc[5][0]=f2fma(d,w.x,acc[5][0]); acc[5][1]=f2fma(d,w.y,acc[5][1]);
            d = dupf(a1.z); acc[6][0]=f2fma(d,w.x,acc[6][0]); acc[6][1]=f2fma(d,w.y,acc[6][1]);
            d = dupf(a1.w); acc[7][0]=f2fma(d,w.x,acc[7][0]); acc[7][1]=f2fma(d,w.y,acc[7][1]);
        }
        if (more) {
            const int nb = buf ^ 1;
            As[nb][lk4+0][lrow] = na0.x; As[nb][lk4+1][lrow] = na0.y;
            As[nb][lk4+2][lrow] = na0.z; As[nb][lk4+3][lrow] = na0.w;
            As[nb][lk4+0][lrow+64] = na1.x; As[nb][lk4+1][lrow+64] = na1.y;
            As[nb][lk4+2][lrow+64] = na1.z; As[nb][lk4+3][lrow+64] = na1.w;
            Wsf[nb][lk4+0][lrow] = nw.x; Wsf[nb][lk4+1][lrow] = nw.y;
            Wsf[nb][lk4+2][lrow] = nw.z; Wsf[nb][lk4+3][lrow] = nw.w;
        }
        __syncthreads();
    }

    const float4 bv = *(const float4*)&bias[n0 + tx * 4];
    #pragma unroll
    for (int i = 0; i < 8; ++i) {
        float2 v0 = unpk(acc[i][0]);
        float2 v1 = unpk(acc[i][1]);
        float4 o;
        o.x = v0.x + bv.x; o.y = v0.y + bv.y;
        o.z = v1.x + bv.z; o.w = v1.y + bv.w;
        const int m = m0 + ty * 8 + i;
        *(float4*)&C[(size_t)m * G3 + n0 + tx * 4] = o;
    }
}

// =====================================================================
// Recurrent scan v6 — pair-split across 2 CTAs per batch-group.
// 128 CTAs x 768 threads; CTA parity p owns units [128p, 128p+128):
// its 384 gate-cols (r/z/n rows of those units) -> combine is LOCAL.
// Only h itself (512 floats each way) is exchanged per step via L2
// mailboxes + t-indexed flags (fence/atomic release-acquire).
// Dot thread = (local col, batch-pair); w packed f32x2 over k-pairs.
// =====================================================================
template<bool WRITE_Y>
__global__ void __launch_bounds__(NTH, 1) scan_kernel(
    const float* __restrict__ xg,
    const float* __restrict__ wA, const float* __restrict__ wB,
    const float* __restrict__ bhh,
    float* __restrict__ y, float* __restrict__ hout,
    float* __restrict__ mail, int* __restrict__ flag)
{
    extern __shared__ ulonglong2 Wsu[];              // [KQ][NCOL]
    __shared__ __align__(16) float hb[4][HPD];       // full hidden state, per batch
    __shared__ __align__(16) float gsum[NCOL][4];    // local gate dots [c][b]
    __shared__ __align__(16) float xst[NCOL][4];     // staged x terms  [c][b]

    const int tid = threadIdx.x;
    const int bid = blockIdx.x;
    const int p   = bid & 1;            // half parity
    const int pr  = bid >> 1;           // pair id (batch group)
    const int bb0 = pr * 4;

    const float* wth = p ? wB : wA;
    const ulonglong2* __restrict__ wtu = (const ulonglong2*)wth;   // [HHQ][NCOL]

    // dot mapping: warps 0-11 -> batch pair 0 (b0,b1), warps 12-23 -> pair 1
    const int c  = (tid < NCOL) ? tid : tid - NCOL;  // local col 0..383
    const int bp = (tid < NCOL) ? 0 : 1;
    const int b0 = bp * 2, b1 = bp * 2 + 1;

    // combine mapping (tid < 512): unit jj, batch cb
    const int jj = tid >> 2;
    const int cb = tid & 3;
    const int gj = p * 128 + jj;                     // global unit
    float br = 0.f, bz = 0.f, bn = 0.f;
    if (tid < 512) {
        br = bhh[gj]; bz = bhh[HH + gj]; bn = bhh[2 * HH + gj];
    }

    // x staging mapping: thread loads local col xc for 2 batches
    const int xc  = tid >> 1;
    const int xb  = (tid & 1) * 2;
    const int xgc = (xc >> 7) * 256 + p * 128 + (xc & 127);   // global gate col
    const size_t STRB  = (size_t)TT * G3;
    const size_t STRBY = (size_t)TT * HH;
    const float* xp0 = xg + (size_t)(bb0 + xb)     * STRB + xgc;
    const float* xp1 = xg + (size_t)(bb0 + xb + 1) * STRB + xgc;

    // mail/flag bases
    float* mail_out = mail + (((size_t)pr * TT) * 2 + p)       * 512;
    const float* mail_in = mail + (((size_t)pr * TT) * 2 + (1 - p)) * 512;
    int* flag_out = flag + ((size_t)pr * TT) * 2 + p;
    int* flag_in  = flag + ((size_t)pr * TT) * 2 + (1 - p);

    // fill smem W cache (coalesced)
    for (int i = tid; i < KQ * NCOL; i += NTH)
        Wsu[i] = wtu[i];
    // zero h
    for (int i = tid; i < 4 * HPD; i += NTH)
        ((float*)hb)[i] = 0.f;
    __syncthreads();

    for (int t = 0; t < TT; ++t) {
        const size_t tofs = (size_t)t * G3;

        // (1) x loads for this step
        float xv0 = xp0[tofs];
        float xv1 = xp1[tofs];

        // (2) streamed-W prefetch, depth 3
        ulonglong2 wq0 = __ldg(wtu + (size_t)KQ * NCOL + c);
        ulonglong2 wq1 = __ldg(wtu + (size_t)(KQ + 1) * NCOL + c);

        u64 a0 = 0, a1 = 0;

        // (3) smem-cached segment
        #pragma unroll
        for (int q = 0; q < KQ; ++q) {
            ulonglong2 w  = Wsu[q * NCOL + c];
            ulonglong2 h0 = *(const ulonglong2*)&hb[b0][4 * q];
            ulonglong2 h1 = *(const ulonglong2*)&hb[b1][4 * q];
            a0 = f2fma(w.x, h0.x, a0); a0 = f2fma(w.y, h0.y, a0);
            a1 = f2fma(w.x, h1.x, a1); a1 = f2fma(w.y, h1.y, a1);
        }

        // (4) streamed segment, depth-3 pipeline
        #pragma unroll
        for (int q = KQ; q < HHQ; ++q) {
            ulonglong2 wn = wq1;
            if (q + 2 < HHQ) wn = __ldg(wtu + (size_t)(q + 2) * NCOL + c);
            ulonglong2 h0 = *(const ulonglong2*)&hb[b0][4 * q];
            ulonglong2 h1 = *(const ulonglong2*)&hb[b1][4 * q];
            a0 = f2fma(wq0.x, h0.x, a0); a0 = f2fma(wq0.y, h0.y, a0);
            a1 = f2fma(wq0.x, h1.x, a1); a1 = f2fma(wq0.y, h1.y, a1);
            wq0 = wq1; wq1 = wn;
        }

        // (5) fold + publish
        { float2 f = unpk(a0); gsum[c][b0] = f.x + f.y; }
        { float2 f = unpk(a1); gsum[c][b1] = f.x + f.y; }
        xst[xc][xb]     = xv0;
        xst[xc][xb + 1] = xv1;
        __syncthreads();

        // (6) combine — fully local (this CTA owns all 3 gates of its units)
        if (tid < 512) {
            const float R  = gsum[jj][cb]       + xst[jj][cb]       + br;
            const float Z  = gsum[128 + jj][cb] + xst[128 + jj][cb] + bz;
            const float Nd = gsum[256 + jj][cb];
            const float xn = xst[256 + jj][cb];
            const float r = sigmf(R);
            const float z = sigmf(Z);
            const float n = tanh_fast(xn + r * (Nd + bn));
            const float hnew = (1.0f - z) * n + z * hb[cb][gj];
            hb[cb][gj] = hnew;
            mail_out[(size_t)t * 1024 + tid] = hnew;   // (pair stride 2*512 per t)
            if (WRITE_Y)
                y[(size_t)(bb0 + cb) * STRBY + (size_t)t * HH + gj] = hnew;
        }
        __syncthreads();

        // (7) release own half / acquire peer half
        if (tid == NTH - 1) {
            __threadfence();
            atomicExch(flag_out + (size_t)t * 2, 1);
        }
        if (tid == NTH - 2) {
            while (atomicAdd(flag_in + (size_t)t * 2, 0) == 0) { }
        }
        __syncthreads();

        // (8) copy peer h-half into local state
        if (tid < 512) {
            hb[cb][(1 - p) * 128 + jj] = mail_in[(size_t)t * 1024 + tid];
        }
        __syncthreads();
    }

    if (!WRITE_Y && tid < 512) {
        hout[(size_t)(bb0 + cb) * HH + gj] = hb[cb][gj];
    }
}

// =====================================================================
// launch
// =====================================================================
extern "C" void kernel_launch(void* const* d_in, const int* in_sizes, int n_in,
                              void* d_out, int out_size)
{
    const float* obs   = (const float*)d_in[0];
    const float* w_ih0 = (const float*)d_in[1];
    const float* w_hh0 = (const float*)d_in[2];
    const float* b_ih0 = (const float*)d_in[3];
    const float* b_hh0 = (const float*)d_in[4];
    const float* w_ih1 = (const float*)d_in[5];
    const float* w_hh1 = (const float*)d_in[6];
    const float* b_ih1 = (const float*)d_in[7];
    const float* b_hh1 = (const float*)d_in[8];
    float* out = (float*)d_out;

    void* xg_p = nullptr;  cudaGetSymbolAddress(&xg_p, g_xg);
    void* y0_p = nullptr;  cudaGetSymbolAddress(&y0_p, g_y0);
    void* wt_p = nullptr;  cudaGetSymbolAddress(&wt_p, g_wth);
    void* ml_p = nullptr;  cudaGetSymbolAddress(&ml_p, g_mail);
    void* fl_p = nullptr;  cudaGetSymbolAddress(&fl_p, g_flag);
    float* xg   = (float*)xg_p;
    float* y0   = (float*)y0_p;
    float* wt   = (float*)wt_p;
    float* mail = (float*)ml_p;
    int*   flag = (int*)fl_p;

    float* wA0 = wt;
    float* wB0 = wA0 + (size_t)NCOL * HH;
    float* wA1 = wB0 + (size_t)NCOL * HH;
    float* wB1 = wA1 + (size_t)NCOL * HH;

    cudaFuncSetAttribute(scan_kernel<true>,  cudaFuncAttributeMaxDynamicSharedMemorySize, SCAN_DSMEM);
    cudaFuncSetAttribute(scan_kernel<false>, cudaFuncAttributeMaxDynamicSharedMemorySize, SCAN_DSMEM);

    const int M = BB * TT;                 // 131072
    dim3 pgrid(G3 / PBN, M / PBM);         // (12, 1024)

    repack_whh<<<G3, HH>>>(w_hh0, wA0, wB0);
    repack_whh<<<G3, HH>>>(w_hh1, wA1, wB1);

    // layer 0
    proj_kernel<<<pgrid, 256>>>(obs, w_ih0, b_ih0, xg, OBS);
    reset_flags<<<64, 1024>>>(flag);
    scan_kernel<true><<<2 * (BB / 4), NTH, SCAN_DSMEM>>>(xg, wA0, wB0, b_hh0, y0, nullptr, mail, flag);
    // layer 1
    proj_kernel<<<pgrid, 256>>>(y0, w_ih1, b_ih1, xg, HH);
    reset_flags<<<64, 1024>>>(flag);
    scan_kernel<false><<<2 * (BB / 4), NTH, SCAN_DSMEM>>>(xg, wA1, wB1, b_hh1, nullptr, out, mail, flag);
}

// round 8
// speedup vs baseline: 2.9877x; 1.6803x over previous
#include <cuda_runtime.h>
#include <cstdint>
#include <cstddef>

// Problem dims
#define BB   256      // batch
#define TT   512      // time
#define OBS  64
#define HH   256      // hidden
#define G3   768      // 3*H
#define HHQ  64       // HH/4 (k-quads)

// split-scan config
#define NTH   384     // threads per scan CTA (12 warps)
#define NCOL  384     // gate-cols per CTA (3 gates x 128 units)
#define NCP   192     // col pairs
#define KQH   16      // quads cached in smem per k-half (32 of 64 total)
#define HPD   264     // hidden-state row stride (floats)
#define SCAN_DSMEM (32 * NCOL * 16)   // 196608 B

typedef unsigned long long u64;

// ---------------- scratch (device globals: allocation-free) ----------------
__device__ float g_xg[(size_t)BB * TT * G3];          // 402 MB gate pre-activations
__device__ float g_y0[(size_t)BB * TT * HH];          // 134 MB layer-0 outputs
__device__ float g_wth[2][2][(size_t)NCOL * HH];      // [layer][half] repacked W_hh
__device__ float g_mail[(size_t)64 * TT * 2 * 512];   // h exchange mailboxes
__device__ int   g_flag[(size_t)64 * TT * 2];         // per-step flags

// ---------------- helpers ----------------
__device__ __forceinline__ u64 dupf(float a) {
    u64 r; asm("mov.b64 %0, {%1,%1};" : "=l"(r) : "f"(a)); return r;
}
__device__ __forceinline__ float2 unpk(u64 v) {
    float2 f; asm("mov.b64 {%0,%1}, %2;" : "=f"(f.x), "=f"(f.y) : "l"(v)); return f;
}
__device__ __forceinline__ u64 f2fma(u64 a, u64 b, u64 c) {
    u64 d; asm("fma.rn.f32x2 %0, %1, %2, %3;" : "=l"(d) : "l"(a), "l"(b), "l"(c)); return d;
}
__device__ __forceinline__ float sigmf(float x) {
    return 1.0f / (1.0f + __expf(-x));
}
__device__ __forceinline__ float tanh_fast(float x) {
    return 1.0f - __fdividef(2.0f, __expf(2.0f * x) + 1.0f);
}
__device__ __forceinline__ int ld_acq(const int* p) {
    int v; asm volatile("ld.global.acquire.gpu.b32 %0, [%1];" : "=r"(v) : "l"(p)); return v;
}

// =====================================================================
// W_hh repack: half p owns units j with (j>>7)==p; local col c = gate*128+(j&127)
//   wth[p][(k>>2)*NCOL*4 + c*4 + (k&3)]   (ulonglong2 view: [quad][c])
// =====================================================================
__global__ void repack_whh(const float* __restrict__ W,
                           float* __restrict__ WA, float* __restrict__ WB)
{
    const int gRow = blockIdx.x;      // 0..767
    const int k    = threadIdx.x;     // 0..255
    const float v  = W[(size_t)gRow * HH + k];
    const int gate = gRow >> 8;
    const int j    = gRow & 255;
    const int p    = j >> 7;
    const int c    = gate * 128 + (j & 127);
    float* out = p ? WB : WA;
    out[(size_t)(k >> 2) * (NCOL * 4) + c * 4 + (k & 3)] = v;
}

__global__ void reset_flags(int* __restrict__ f)
{
    f[blockIdx.x * 1024 + threadIdx.x] = 0;
}

// =====================================================================
// Projection GEMM: C[M][768] = A[M][K] @ W[768][K]^T + bias[768]
// =====================================================================
#define PBM 128
#define PBN 64
#define PBK 16

__global__ void __launch_bounds__(256) proj_kernel(
    const float* __restrict__ A, const float* __restrict__ Wt,
    const float* __restrict__ bias, float* __restrict__ C, int K)
{
    __shared__ float As[2][PBK][PBM];
    __shared__ float Wsf[2][PBK][PBN];

    const int tid = threadIdx.x;
    const int tx = tid & 15;
    const int ty = tid >> 4;
    const int m0 = blockIdx.y * PBM;
    const int n0 = blockIdx.x * PBN;

    const int lrow = tid >> 2;
    const int lk4  = (tid & 3) << 2;
    const float* Ag0 = A  + (size_t)(m0 + lrow)      * K + lk4;
    const float* Ag1 = A  + (size_t)(m0 + lrow + 64) * K + lk4;
    const float* Wg  = Wt + (size_t)(n0 + lrow)      * K + lk4;

    u64 acc[8][2];
    #pragma unroll
    for (int i = 0; i < 8; ++i) { acc[i][0] = 0ULL; acc[i][1] = 0ULL; }

    const int panels = K >> 4;
    {
        float4 va0 = *(const float4*)(Ag0);
        float4 va1 = *(const float4*)(Ag1);
        float4 vw  = *(const float4*)(Wg);
        As[0][lk4+0][lrow] = va0.x; As[0][lk4+1][lrow] = va0.y;
        As[0][lk4+2][lrow] = va0.z; As[0][lk4+3][lrow] = va0.w;
        As[0][lk4+0][lrow+64] = va1.x; As[0][lk4+1][lrow+64] = va1.y;
        As[0][lk4+2][lrow+64] = va1.z; As[0][lk4+3][lrow+64] = va1.w;
        Wsf[0][lk4+0][lrow] = vw.x; Wsf[0][lk4+1][lrow] = vw.y;
        Wsf[0][lk4+2][lrow] = vw.z; Wsf[0][lk4+3][lrow] = vw.w;
    }
    __syncthreads();

    for (int p = 0; p < panels; ++p) {
        const int buf = p & 1;
        float4 na0, na1, nw;
        const bool more = (p + 1 < panels);
        if (more) {
            const int k0 = (p + 1) << 4;
            na0 = *(const float4*)(Ag0 + k0);
            na1 = *(const float4*)(Ag1 + k0);
            nw  = *(const float4*)(Wg  + k0);
        }
        #pragma unroll
        for (int k = 0; k < PBK; ++k) {
            float4 a0 = *(const float4*)&As[buf][k][ty * 8];
            float4 a1 = *(const float4*)&As[buf][k][ty * 8 + 4];
            ulonglong2 w = *(const ulonglong2*)&Wsf[buf][k][tx * 4];
            u64 d;
            d = dupf(a0.x); acc[0][0]=f2fma(d,w.x,acc[0][0]); acc[0][1]=f2fma(d,w.y,acc[0][1]);
            d = dupf(a0.y); acc[1][0]=f2fma(d,w.x,acc[1][0]); acc[1][1]=f2fma(d,w.y,acc[1][1]);
            d = dupf(a0.z); acc[2][0]=f2fma(d,w.x,acc[2][0]); acc[2][1]=f2fma(d,w.y,acc[2][1]);
            d = dupf(a0.w); acc[3][0]=f2fma(d,w.x,acc[3][0]); acc[3][1]=f2fma(d,w.y,acc[3][1]);
            d = dupf(a1.x); acc[4][0]=f2fma(d,w.x,acc[4][0]); acc[4][1]=f2fma(d,w.y,acc[4][1]);
            d = dupf(a1.y); acc[5][0]=f2fma(d,w.x,acc[5][0]); acc[5][1]=f2fma(d,w.y,acc[5][1]);
            d = dupf(a1.z); acc[6][0]=f2fma(d,w.x,acc[6][0]); acc[6][1]=f2fma(d,w.y,acc[6][1]);
            d = dupf(a1.w); acc[7][0]=f2fma(d,w.x,acc[7][0]); acc[7][1]=f2fma(d,w.y,acc[7][1]);
        }
        if (more) {
            const int nb = buf ^ 1;
            As[nb][lk4+0][lrow] = na0.x; As[nb][lk4+1][lrow] = na0.y;
            As[nb][lk4+2][lrow] = na0.z; As[nb][lk4+3][lrow] = na0.w;
            As[nb][lk4+0][lrow+64] = na1.x; As[nb][lk4+1][lrow+64] = na1.y;
            As[nb][lk4+2][lrow+64] = na1.z; As[nb][lk4+3][lrow+64] = na1.w;
            Wsf[nb][lk4+0][lrow] = nw.x; Wsf[nb][lk4+1][lrow] = nw.y;
            Wsf[nb][lk4+2][lrow] = nw.z; Wsf[nb][lk4+3][lrow] = nw.w;
        }
        __syncthreads();
    }

    const float4 bv = *(const float4*)&bias[n0 + tx * 4];
    #pragma unroll
    for (int i = 0; i < 8; ++i) {
        float2 v0 = unpk(acc[i][0]);
        float2 v1 = unpk(acc[i][1]);
        float4 o;
        o.x = v0.x + bv.x; o.y = v0.y + bv.y;
        o.z = v1.x + bv.z; o.w = v1.y + bv.w;
        const int m = m0 + ty * 8 + i;
        *(float4*)&C[(size_t)m * G3 + n0 + tx * 4] = o;
    }
}

// =====================================================================
// Recurrent scan v7 — pair-split + k-half warp groups.
// 128 CTAs x 384 threads. CTA parity p owns units [128p,128p+128).
// Thread = (col-pair cp, k-half kh): cols cp, cp+192; 4 batches;
// quads [32kh, 32kh+32). W read exactly once per CTA per step.
// Warps with kh==p (own half) start immediately after combine; the
// kh==1-p warps wait for the partner's h-half mail — the L2 exchange
// round trip hides under the own-half FMA stream.
// =====================================================================
template<bool WRITE_Y>
__global__ void __launch_bounds__(NTH, 1) scan_kernel(
    const float* __restrict__ xg,
    const float* __restrict__ wA, const float* __restrict__ wB,
    const float* __restrict__ bhh,
    float* __restrict__ y, float* __restrict__ hout,
    float* __restrict__ mail, int* __restrict__ flag)
{
    extern __shared__ ulonglong2 Wsq[];               // [32][NCOL] cached quads
    __shared__ __align__(16) float hb[4][HPD];        // full hidden state per batch
    __shared__ __align__(16) float gsumP[2][NCOL][4]; // partial dots [khalf][col][batch]
    __shared__ __align__(16) float xst[NCOL][4];      // staged x terms [col][batch]

    const int tid = threadIdx.x;
    const int bid = blockIdx.x;
    const int p   = bid & 1;             // own unit-half parity
    const int pr  = bid >> 1;            // pair id (batch group)
    const int bb0 = pr * 4;
    const int pp  = 1 - p;               // peer parity

    const int cp  = tid % NCP;           // col pair 0..191
    const int kh  = tid / NCP;           // k-half 0/1
    const int c0  = cp;
    const int c1  = cp + NCP;
    const int qb  = kh * 32;             // absolute quad base
    const int rowb = kh * KQH;           // smem cache row base
    const bool is_peer = (kh != p);

    const float* wth = p ? wB : wA;
    const ulonglong2* __restrict__ wtu = (const ulonglong2*)wth;   // [HHQ][NCOL]

    // fill smem W cache: rows [kh*16 + ql] = absolute quad kh*32 + ql, ql<16
    for (int i = tid; i < 32 * NCOL; i += NTH) {
        const int row = i / NCOL, c = i % NCOL;
        const int khr = row / KQH, ql = row % KQH;
        Wsq[i] = wtu[(size_t)(khr * 32 + ql) * NCOL + c];
    }
    // zero h
    for (int i = tid; i < 4 * HPD; i += NTH)
        ((float*)hb)[i] = 0.f;

    // combine constants (threads 0..255: unit jj = tid>>1, batches (tid&1)*2 +{0,1})
    const int jj  = tid >> 1;
    const int cb0 = (tid & 1) * 2;
    const int gj  = p * 128 + jj;
    float br = 0.f, bz = 0.f, bn = 0.f;
    if (tid < 256) {
        br = bhh[gj]; bz = bhh[HH + gj]; bn = bhh[2 * HH + gj];
    }

    // x staging: thread loads local col = tid for 4 batches
    const int xgc = (tid >> 7) * 256 + p * 128 + (tid & 127);
    const size_t STRB  = (size_t)TT * G3;
    const size_t STRBY = (size_t)TT * HH;
    const float* xp = xg + (size_t)bb0 * STRB + xgc;

    // mail/flag bases
    float* mail_out = mail + (((size_t)pr * TT) * 2 + p)  * 512;
    const float* mail_in = mail + (((size_t)pr * TT) * 2 + pp) * 512;
    int* flag_base = flag + (size_t)pr * TT * 2;
    const int relTid = NCP * p;          // first own-group thread releases

    __syncthreads();

    for (int t = 0; t < TT; ++t) {
        const size_t tofs = (size_t)t * G3;

        // release previous step's own half (after end-of-step barrier)
        if (t > 0 && tid == relTid) {
            __threadfence();
            atomicExch(flag_base + (size_t)(t - 1) * 2 + p, 1);
        }

        // x loads for this step (in flight across the whole dot)
        float xv0 = xp[tofs];
        float xv1 = xp[STRB + tofs];
        float xv2 = xp[2 * STRB + tofs];
        float xv3 = xp[3 * STRB + tofs];

        // streamed-W prefetch (independent of mail; issued before any spin)
        const ulonglong2* ws0 = wtu + (size_t)(qb + KQH) * NCOL;
        const ulonglong2* ws1 = wtu + (size_t)(qb + KQH + 1) * NCOL;
        ulonglong2 p0a = __ldg(ws0 + c0), p0b = __ldg(ws0 + c1);
        ulonglong2 p1a = __ldg(ws1 + c0), p1b = __ldg(ws1 + c1);

        // peer-half warps: acquire partner h(t-1), copy into hb
        if (is_peer && t > 0) {
            const int* fp = flag_base + (size_t)(t - 1) * 2 + pp;
            while (ld_acq(fp) == 0) { }
            const float* mi = mail_in + (size_t)(t - 1) * 1024;
            const int lt = tid - NCP * pp;
            #pragma unroll
            for (int r = 0; r < 3; ++r) {
                const int idx = lt + NCP * r;
                if (idx < 512) {
                    hb[idx & 3][pp * 128 + (idx >> 2)] = mi[idx];
                }
            }
            asm volatile("bar.sync 1, %0;" :: "n"(NCP) : "memory");
        }

        u64 aA0=0, aA1=0, aA2=0, aA3=0;   // col c0, batches 0..3 (k-pair lanes)
        u64 aB0=0, aB1=0, aB2=0, aB3=0;   // col c1

        // cached segment (16 quads)
        #pragma unroll
        for (int q = 0; q < KQH; ++q) {
            const int qa = qb + q;
            ulonglong2 wa = Wsq[(rowb + q) * NCOL + c0];
            ulonglong2 wb = Wsq[(rowb + q) * NCOL + c1];
            ulonglong2 h0 = *(const ulonglong2*)&hb[0][4 * qa];
            ulonglong2 h1 = *(const ulonglong2*)&hb[1][4 * qa];
            ulonglong2 h2 = *(const ulonglong2*)&hb[2][4 * qa];
            ulonglong2 h3 = *(const ulonglong2*)&hb[3][4 * qa];
            aA0 = f2fma(wa.x, h0.x, aA0); aA0 = f2fma(wa.y, h0.y, aA0);
            aA1 = f2fma(wa.x, h1.x, aA1); aA1 = f2fma(wa.y, h1.y, aA1);
            aA2 = f2fma(wa.x, h2.x, aA2); aA2 = f2fma(wa.y, h2.y, aA2);
            aA3 = f2fma(wa.x, h3.x, aA3); aA3 = f2fma(wa.y, h3.y, aA3);
            aB0 = f2fma(wb.x, h0.x, aB0); aB0 = f2fma(wb.y, h0.y, aB0);
            aB1 = f2fma(wb.x, h1.x, aB1); aB1 = f2fma(wb.y, h1.y, aB1);
            aB2 = f2fma(wb.x, h2.x, aB2); aB2 = f2fma(wb.y, h2.y, aB2);
            aB3 = f2fma(wb.x, h3.x, aB3); aB3 = f2fma(wb.y, h3.y, aB3);
        }

        // streamed segment (16 quads), depth-2 rolling prefetch
        #pragma unroll
        for (int q = KQH; q < 32; ++q) {
            const int qa = qb + q;
            ulonglong2 cwa = p0a, cwb = p0b;
            p0a = p1a; p0b = p1b;
            if (q + 2 < 32) {
                const ulonglong2* wn = wtu + (size_t)(qa + 2) * NCOL;
                p1a = __ldg(wn + c0); p1b = __ldg(wn + c1);
            }
            ulonglong2 h0 = *(const ulonglong2*)&hb[0][4 * qa];
            ulonglong2 h1 = *(const ulonglong2*)&hb[1][4 * qa];
            ulonglong2 h2 = *(const ulonglong2*)&hb[2][4 * qa];
            ulonglong2 h3 = *(const ulonglong2*)&hb[3][4 * qa];
            aA0 = f2fma(cwa.x, h0.x, aA0); aA0 = f2fma(cwa.y, h0.y, aA0);
            aA1 = f2fma(cwa.x, h1.x, aA1); aA1 = f2fma(cwa.y, h1.y, aA1);
            aA2 = f2fma(cwa.x, h2.x, aA2); aA2 = f2fma(cwa.y, h2.y, aA2);
            aA3 = f2fma(cwa.x, h3.x, aA3); aA3 = f2fma(cwa.y, h3.y, aA3);
            aB0 = f2fma(cwb.x, h0.x, aB0); aB0 = f2fma(cwb.y, h0.y, aB0);
            aB1 = f2fma(cwb.x, h1.x, aB1); aB1 = f2fma(cwb.y, h1.y, aB1);
            aB2 = f2fma(cwb.x, h2.x, aB2); aB2 = f2fma(cwb.y, h2.y, aB2);
            aB3 = f2fma(cwb.x, h3.x, aB3); aB3 = f2fma(cwb.y, h3.y, aB3);
        }

        // fold k-pair lanes, publish partials (STS.128, coalesced)
        {
            float2 f0 = unpk(aA0), f1 = unpk(aA1), f2 = unpk(aA2), f3 = unpk(aA3);
            *(float4*)&gsumP[kh][c0][0] =
                make_float4(f0.x + f0.y, f1.x + f1.y, f2.x + f2.y, f3.x + f3.y);
        }
        {
            float2 f0 = unpk(aB0), f1 = unpk(aB1), f2 = unpk(aB2), f3 = unpk(aB3);
            *(float4*)&gsumP[kh][c1][0] =
                make_float4(f0.x + f0.y, f1.x + f1.y, f2.x + f2.y, f3.x + f3.y);
        }
        *(float4*)&xst[tid][0] = make_float4(xv0, xv1, xv2, xv3);
        __syncthreads();

        // combine: 256 threads, 2 (unit,batch) items each
        if (tid < 256) {
            float2 R0 = *(const float2*)&gsumP[0][jj][cb0];
            float2 R1 = *(const float2*)&gsumP[1][jj][cb0];
            float2 Z0 = *(const float2*)&gsumP[0][128 + jj][cb0];
            float2 Z1 = *(const float2*)&gsumP[1][128 + jj][cb0];
            float2 N0 = *(const float2*)&gsumP[0][256 + jj][cb0];
            float2 N1 = *(const float2*)&gsumP[1][256 + jj][cb0];
            float2 XR = *(const float2*)&xst[jj][cb0];
            float2 XZ = *(const float2*)&xst[128 + jj][cb0];
            float2 XN = *(const float2*)&xst[256 + jj][cb0];

            const float r0 = sigmf(R0.x + R1.x + XR.x + br);
            const float z0 = sigmf(Z0.x + Z1.x + XZ.x + bz);
            const float n0 = tanh_fast(XN.x + r0 * (N0.x + N1.x + bn));
            const float h0 = (1.0f - z0) * n0 + z0 * hb[cb0][gj];
            hb[cb0][gj] = h0;

            const float r1 = sigmf(R0.y + R1.y + XR.y + br);
            const float z1 = sigmf(Z0.y + Z1.y + XZ.y + bz);
            const float n1 = tanh_fast(XN.y + r1 * (N0.y + N1.y + bn));
            const float h1 = (1.0f - z1) * n1 + z1 * hb[cb0 + 1][gj];
            hb[cb0 + 1][gj] = h1;

            *(float2*)&mail_out[(size_t)t * 1024 + 2 * tid] = make_float2(h0, h1);
            if (WRITE_Y) {
                y[(size_t)(bb0 + cb0)     * STRBY + (size_t)t * HH + gj] = h0;
                y[(size_t)(bb0 + cb0 + 1) * STRBY + (size_t)t * HH + gj] = h1;
            }
        }
        __syncthreads();
    }

    if (!WRITE_Y && tid < 256) {
        hout[(size_t)(bb0 + cb0)     * HH + gj] = hb[cb0][gj];
        hout[(size_t)(bb0 + cb0 + 1) * HH + gj] = hb[cb0 + 1][gj];
    }
}

// =====================================================================
// launch
// =====================================================================
extern "C" void kernel_launch(void* const* d_in, const int* in_sizes, int n_in,
                              void* d_out, int out_size)
{
    const float* obs   = (const float*)d_in[0];
    const float* w_ih0 = (const float*)d_in[1];
    const float* w_hh0 = (const float*)d_in[2];
    const float* b_ih0 = (const float*)d_in[3];
    const float* b_hh0 = (const float*)d_in[4];
    const float* w_ih1 = (const float*)d_in[5];
    const float* w_hh1 = (const float*)d_in[6];
    const float* b_ih1 = (const float*)d_in[7];
    const float* b_hh1 = (const float*)d_in[8];
    float* out = (float*)d_out;

    void* xg_p = nullptr;  cudaGetSymbolAddress(&xg_p, g_xg);
    void* y0_p = nullptr;  cudaGetSymbolAddress(&y0_p, g_y0);
    void* wt_p = nullptr;  cudaGetSymbolAddress(&wt_p, g_wth);
    void* ml_p = nullptr;  cudaGetSymbolAddress(&ml_p, g_mail);
    void* fl_p = nullptr;  cudaGetSymbolAddress(&fl_p, g_flag);
    float* xg   = (float*)xg_p;
    float* y0   = (float*)y0_p;
    float* wt   = (float*)wt_p;
    float* mail = (float*)ml_p;
    int*   flag = (int*)fl_p;

    float* wA0 = wt;
    float* wB0 = wA0 + (size_t)NCOL * HH;
    float* wA1 = wB0 + (size_t)NCOL * HH;
    float* wB1 = wA1 + (size_t)NCOL * HH;

    cudaFuncSetAttribute(scan_kernel<true>,  cudaFuncAttributeMaxDynamicSharedMemorySize, SCAN_DSMEM);
    cudaFuncSetAttribute(scan_kernel<false>, cudaFuncAttributeMaxDynamicSharedMemorySize, SCAN_DSMEM);

    const int M = BB * TT;                 // 131072
    dim3 pgrid(G3 / PBN, M / PBM);         // (12, 1024)

    repack_whh<<<G3, HH>>>(w_hh0, wA0, wB0);
    repack_whh<<<G3, HH>>>(w_hh1, wA1, wB1);

    // layer 0
    proj_kernel<<<pgrid, 256>>>(obs, w_ih0, b_ih0, xg, OBS);
    reset_flags<<<64, 1024>>>(flag);
    scan_kernel<true><<<2 * (BB / 4), NTH, SCAN_DSMEM>>>(xg, wA0, wB0, b_hh0, y0, nullptr, mail, flag);
    // layer 1
    proj_kernel<<<pgrid, 256>>>(y0, w_ih1, b_ih1, xg, HH);
    reset_flags<<<64, 1024>>>(flag);
    scan_kernel<false><<<2 * (BB / 4), NTH, SCAN_DSMEM>>>(xg, wA1, wB1, b_hh1, nullptr, out, mail, flag);
}

// round 9
// speedup vs baseline: 3.1986x; 1.0706x over previous
#include <cuda_runtime.h>
#include <cstdint>
#include <cstddef>

// Problem dims
#define BB   256      // batch
#define TT   512      // time
#define OBS  64
#define HH   256      // hidden
#define G3   768      // 3*H
#define HHQ  64       // HH/4 (k-quads)

// split-scan config
#define NTH   384     // threads per scan CTA (12 warps)
#define NCOL  384     // gate-cols per CTA (3 gates x 128 units)
#define NCP   192     // col pairs
#define KQH   16      // quads cached in smem per k-half (32 of 64 total)
#define HPD   264     // hidden-state row stride (floats)
#define SCAN_DSMEM (32 * NCOL * 16)   // 196608 B

typedef unsigned long long u64;

// ---------------- scratch (device globals: allocation-free) ----------------
__device__ float g_xg[(size_t)BB * TT * G3];          // 402 MB gate pre-activations
__device__ float g_y0[(size_t)BB * TT * HH];          // 134 MB layer-0 outputs
__device__ float g_wth[2][2][(size_t)NCOL * HH];      // [layer][half] repacked W_hh
__device__ float g_mail[(size_t)64 * TT * 2 * 512];   // h exchange mailboxes
__device__ int   g_flag[2][(size_t)64 * TT * 2];      // per-layer per-step flags

// ---------------- helpers ----------------
__device__ __forceinline__ float2 unpk(u64 v) {
    float2 f; asm("mov.b64 {%0,%1}, %2;" : "=f"(f.x), "=f"(f.y) : "l"(v)); return f;
}
__device__ __forceinline__ u64 f2fma(u64 a, u64 b, u64 c) {
    u64 d; asm("fma.rn.f32x2 %0, %1, %2, %3;" : "=l"(d) : "l"(a), "l"(b), "l"(c)); return d;
}
__device__ __forceinline__ float sigmf(float x) {
    return 1.0f / (1.0f + __expf(-x));
}
__device__ __forceinline__ float tanh_fast(float x) {
    return 1.0f - __fdividef(2.0f, __expf(2.0f * x) + 1.0f);
}
__device__ __forceinline__ int ld_acq(const int* p) {
    int v; asm volatile("ld.global.acquire.gpu.b32 %0, [%1];" : "=r"(v) : "l"(p)); return v;
}
__device__ __forceinline__ uint32_t cvt_tf32(float x) {
    uint32_t r; asm("cvt.rna.tf32.f32 %0, %1;" : "=r"(r) : "f"(x)); return r;
}
__device__ __forceinline__ void mma_tf32(float* c, const uint32_t* a, const uint32_t* b) {
    asm volatile(
        "mma.sync.aligned.m16n8k8.row.col.f32.tf32.tf32.f32 "
        "{%0,%1,%2,%3}, {%4,%5,%6,%7}, {%8,%9}, {%0,%1,%2,%3};"
        : "+f"(c[0]), "+f"(c[1]), "+f"(c[2]), "+f"(c[3])
        : "r"(a[0]), "r"(a[1]), "r"(a[2]), "r"(a[3]), "r"(b[0]), "r"(b[1]));
}

// =====================================================================
// W_hh repack: half p owns units j with (j>>7)==p; local col c = gate*128+(j&127)
// =====================================================================
__global__ void repack_whh(const float* __restrict__ W,
                           float* __restrict__ WA, float* __restrict__ WB)
{
    const int gRow = blockIdx.x;      // 0..767
    const int k    = threadIdx.x;     // 0..255
    const float v  = W[(size_t)gRow * HH + k];
    const int gate = gRow >> 8;
    const int j    = gRow & 255;
    const int p    = j >> 7;
    const int c    = gate * 128 + (j & 127);
    float* out = p ? WB : WA;
    out[(size_t)(k >> 2) * (NCOL * 4) + c * 4 + (k & 3)] = v;
}

__global__ void reset_flags(int* __restrict__ f)
{
    f[blockIdx.x * 1024 + threadIdx.x] = 0;
}

// =====================================================================
// Projection GEMM (tf32 tensor cores):
//   C[M][768] = A[M][K] @ W[768][K]^T + bias[768]
// Tile 128x64xK, BK=32; 256 threads = 8 warps (4x2), warp tile 32x32,
// mma.sync.m16n8k8 tf32 (2 m-tiles x 4 n-tiles per warp).
// =====================================================================
#define TBM 128
#define TBN 64
#define TBK 32

__global__ void __launch_bounds__(256) proj_tf32(
    const float* __restrict__ A, const float* __restrict__ Wt,
    const float* __restrict__ bias, float* __restrict__ C, int K)
{
    __shared__ float As[TBK][TBM + 4];   // k-major A tile
    __shared__ float Bs[TBK][TBN + 4];   // k-major B tile

    const int tid  = threadIdx.x;
    const int lane = tid & 31;
    const int warp = tid >> 5;
    const int wm   = warp & 3;           // 0..3 -> m offset 32*wm
    const int wn   = warp >> 2;          // 0..1 -> n offset 32*wn
    const int gid  = lane >> 2;          // 0..7
    const int tig  = lane & 3;           // 0..3
    const int m0   = blockIdx.y * TBM;
    const int n0   = blockIdx.x * TBN;

    float acc[2][4][4];
    #pragma unroll
    for (int mt = 0; mt < 2; ++mt)
        #pragma unroll
        for (int nt = 0; nt < 4; ++nt)
            #pragma unroll
            for (int r = 0; r < 4; ++r) acc[mt][nt][r] = 0.f;

    for (int k0 = 0; k0 < K; k0 += TBK) {
        // stage A (128x32) transposed to k-major
        #pragma unroll
        for (int i = 0; i < 4; ++i) {
            const int linear = tid + i * 256;      // 0..1023
            const int row = linear >> 3;           // 0..127
            const int kq  = (linear & 7) << 2;     // 0,4,..,28
            float4 v = *(const float4*)&A[(size_t)(m0 + row) * K + k0 + kq];
            As[kq + 0][row] = v.x; As[kq + 1][row] = v.y;
            As[kq + 2][row] = v.z; As[kq + 3][row] = v.w;
        }
        // stage B (64x32) transposed to k-major
        #pragma unroll
        for (int i = 0; i < 2; ++i) {
            const int linear = tid + i * 256;      // 0..511
            const int row = linear >> 3;           // 0..63
            const int kq  = (linear & 7) << 2;
            float4 v = *(const float4*)&Wt[(size_t)(n0 + row) * K + k0 + kq];
            Bs[kq + 0][row] = v.x; Bs[kq + 1][row] = v.y;
            Bs[kq + 2][row] = v.z; Bs[kq + 3][row] = v.w;
        }
        __syncthreads();

        #pragma unroll
        for (int ks = 0; ks < TBK; ks += 8) {
            uint32_t af[2][4], bf[4][2];
            #pragma unroll
            for (int mt = 0; mt < 2; ++mt) {
                const int rm = wm * 32 + mt * 16 + gid;
                af[mt][0] = cvt_tf32(As[ks + tig][rm]);
                af[mt][1] = cvt_tf32(As[ks + tig][rm + 8]);
                af[mt][2] = cvt_tf32(As[ks + tig + 4][rm]);
                af[mt][3] = cvt_tf32(As[ks + tig + 4][rm + 8]);
            }
            #pragma unroll
            for (int nt = 0; nt < 4; ++nt) {
                const int nb = wn * 32 + nt * 8 + gid;
                bf[nt][0] = cvt_tf32(Bs[ks + tig][nb]);
                bf[nt][1] = cvt_tf32(Bs[ks + tig + 4][nb]);
            }
            #pragma unroll
            for (int mt = 0; mt < 2; ++mt)
                #pragma unroll
                for (int nt = 0; nt < 4; ++nt)
                    mma_tf32(acc[mt][nt], af[mt], bf[nt]);
        }
        __syncthreads();
    }

    // epilogue: bias + store
    #pragma unroll
    for (int mt = 0; mt < 2; ++mt) {
        const int rm = m0 + wm * 32 + mt * 16 + gid;
        #pragma unroll
        for (int nt = 0; nt < 4; ++nt) {
            const int nc = n0 + wn * 32 + nt * 8 + 2 * tig;
            const float b0 = bias[nc], b1 = bias[nc + 1];
            *(float2*)&C[(size_t)rm * G3 + nc] =
                make_float2(acc[mt][nt][0] + b0, acc[mt][nt][1] + b1);
            *(float2*)&C[(size_t)(rm + 8) * G3 + nc] =
                make_float2(acc[mt][nt][2] + b0, acc[mt][nt][3] + b1);
        }
    }
}

// =====================================================================
// Recurrent scan v7 (UNCHANGED from R8) — pair-split + k-half warp groups.
// =====================================================================
template<bool WRITE_Y>
__global__ void __launch_bounds__(NTH, 1) scan_kernel(
    const float* __restrict__ xg,
    const float* __restrict__ wA, const float* __restrict__ wB,
    const float* __restrict__ bhh,
    float* __restrict__ y, float* __restrict__ hout,
    float* __restrict__ mail, int* __restrict__ flag)
{
    extern __shared__ ulonglong2 Wsq[];               // [32][NCOL] cached quads
    __shared__ __align__(16) float hb[4][HPD];        // full hidden state per batch
    __shared__ __align__(16) float gsumP[2][NCOL][4]; // partial dots [khalf][col][batch]
    __shared__ __align__(16) float xst[NCOL][4];      // staged x terms [col][batch]

    const int tid = threadIdx.x;
    const int bid = blockIdx.x;
    const int p   = bid & 1;             // own unit-half parity
    const int pr  = bid >> 1;            // pair id (batch group)
    const int bb0 = pr * 4;
    const int pp  = 1 - p;               // peer parity

    const int cp  = tid % NCP;           // col pair 0..191
    const int kh  = tid / NCP;           // k-half 0/1
    const int c0  = cp;
    const int c1  = cp + NCP;
    const int qb  = kh * 32;             // absolute quad base
    const int rowb = kh * KQH;           // smem cache row base
    const bool is_peer = (kh != p);

    const float* wth = p ? wB : wA;
    const ulonglong2* __restrict__ wtu = (const ulonglong2*)wth;   // [HHQ][NCOL]

    for (int i = tid; i < 32 * NCOL; i += NTH) {
        const int row = i / NCOL, c = i % NCOL;
        const int khr = row / KQH, ql = row % KQH;
        Wsq[i] = wtu[(size_t)(khr * 32 + ql) * NCOL + c];
    }
    for (int i = tid; i < 4 * HPD; i += NTH)
        ((float*)hb)[i] = 0.f;

    const int jj  = tid >> 1;
    const int cb0 = (tid & 1) * 2;
    const int gj  = p * 128 + jj;
    float br = 0.f, bz = 0.f, bn = 0.f;
    if (tid < 256) {
        br = bhh[gj]; bz = bhh[HH + gj]; bn = bhh[2 * HH + gj];
    }

    const int xgc = (tid >> 7) * 256 + p * 128 + (tid & 127);
    const size_t STRB  = (size_t)TT * G3;
    const size_t STRBY = (size_t)TT * HH;
    const float* xp = xg + (size_t)bb0 * STRB + xgc;

    float* mail_out = mail + (((size_t)pr * TT) * 2 + p)  * 512;
    const float* mail_in = mail + (((size_t)pr * TT) * 2 + pp) * 512;
    int* flag_base = flag + (size_t)pr * TT * 2;
    const int relTid = NCP * p;

    __syncthreads();

    for (int t = 0; t < TT; ++t) {
        const size_t tofs = (size_t)t * G3;

        if (t > 0 && tid == relTid) {
            __threadfence();
            atomicExch(flag_base + (size_t)(t - 1) * 2 + p, 1);
        }

        float xv0 = xp[tofs];
        float xv1 = xp[STRB + tofs];
        float xv2 = xp[2 * STRB + tofs];
        float xv3 = xp[3 * STRB + tofs];

        const ulonglong2* ws0 = wtu + (size_t)(qb + KQH) * NCOL;
        const ulonglong2* ws1 = wtu + (size_t)(qb + KQH + 1) * NCOL;
        ulonglong2 p0a = __ldg(ws0 + c0), p0b = __ldg(ws0 + c1);
        ulonglong2 p1a = __ldg(ws1 + c0), p1b = __ldg(ws1 + c1);

        if (is_peer && t > 0) {
            const int* fp = flag_base + (size_t)(t - 1) * 2 + pp;
            while (ld_acq(fp) == 0) { }
            const float* mi = mail_in + (size_t)(t - 1) * 1024;
            const int lt = tid - NCP * pp;
            #pragma unroll
            for (int r = 0; r < 3; ++r) {
                const int idx = lt + NCP * r;
                if (idx < 512) {
                    hb[idx & 3][pp * 128 + (idx >> 2)] = mi[idx];
                }
            }
            asm volatile("bar.sync 1, %0;" :: "n"(NCP) : "memory");
        }

        u64 aA0=0, aA1=0, aA2=0, aA3=0;
        u64 aB0=0, aB1=0, aB2=0, aB3=0;

        #pragma unroll
        for (int q = 0; q < KQH; ++q) {
            const int qa = qb + q;
            ulonglong2 wa = Wsq[(rowb + q) * NCOL + c0];
            ulonglong2 wb = Wsq[(rowb + q) * NCOL + c1];
            ulonglong2 h0 = *(const ulonglong2*)&hb[0][4 * qa];
            ulonglong2 h1 = *(const ulonglong2*)&hb[1][4 * qa];
            ulonglong2 h2 = *(const ulonglong2*)&hb[2][4 * qa];
            ulonglong2 h3 = *(const ulonglong2*)&hb[3][4 * qa];
            aA0 = f2fma(wa.x, h0.x, aA0); aA0 = f2fma(wa.y, h0.y, aA0);
            aA1 = f2fma(wa.x, h1.x, aA1); aA1 = f2fma(wa.y, h1.y, aA1);
            aA2 = f2fma(wa.x, h2.x, aA2); aA2 = f2fma(wa.y, h2.y, aA2);
            aA3 = f2fma(wa.x, h3.x, aA3); aA3 = f2fma(wa.y, h3.y, aA3);
            aB0 = f2fma(wb.x, h0.x, aB0); aB0 = f2fma(wb.y, h0.y, aB0);
            aB1 = f2fma(wb.x, h1.x, aB1); aB1 = f2fma(wb.y, h1.y, aB1);
            aB2 = f2fma(wb.x, h2.x, aB2); aB2 = f2fma(wb.y, h2.y, aB2);
            aB3 = f2fma(wb.x, h3.x, aB3); aB3 = f2fma(wb.y, h3.y, aB3);
        }

        #pragma unroll
        for (int q = KQH; q < 32; ++q) {
            const int qa = qb + q;
            ulonglong2 cwa = p0a, cwb = p0b;
            p0a = p1a; p0b = p1b;
            if (q + 2 < 32) {
                const ulonglong2* wn = wtu + (size_t)(qa + 2) * NCOL;
                p1a = __ldg(wn + c0); p1b = __ldg(wn + c1);
            }
            ulonglong2 h0 = *(const ulonglong2*)&hb[0][4 * qa];
            ulonglong2 h1 = *(const ulonglong2*)&hb[1][4 * qa];
            ulonglong2 h2 = *(const ulonglong2*)&hb[2][4 * qa];
            ulonglong2 h3 = *(const ulonglong2*)&hb[3][4 * qa];
            aA0 = f2fma(cwa.x, h0.x, aA0); aA0 = f2fma(cwa.y, h0.y, aA0);
            aA1 = f2fma(cwa.x, h1.x, aA1); aA1 = f2fma(cwa.y, h1.y, aA1);
            aA2 = f2fma(cwa.x, h2.x, aA2); aA2 = f2fma(cwa.y, h2.y, aA2);
            aA3 = f2fma(cwa.x, h3.x, aA3); aA3 = f2fma(cwa.y, h3.y, aA3);
            aB0 = f2fma(cwb.x, h0.x, aB0); aB0 = f2fma(cwb.y, h0.y, aB0);
            aB1 = f2fma(cwb.x, h1.x, aB1); aB1 = f2fma(cwb.y, h1.y, aB1);
            aB2 = f2fma(cwb.x, h2.x, aB2); aB2 = f2fma(cwb.y, h2.y, aB2);
            aB3 = f2fma(cwb.x, h3.x, aB3); aB3 = f2fma(cwb.y, h3.y, aB3);
        }

        {
            float2 f0 = unpk(aA0), f1 = unpk(aA1), f2 = unpk(aA2), f3 = unpk(aA3);
            *(float4*)&gsumP[kh][c0][0] =
                make_float4(f0.x + f0.y, f1.x + f1.y, f2.x + f2.y, f3.x + f3.y);
        }
        {
            float2 f0 = unpk(aB0), f1 = unpk(aB1), f2 = unpk(aB2), f3 = unpk(aB3);
            *(float4*)&gsumP[kh][c1][0] =
                make_float4(f0.x + f0.y, f1.x + f1.y, f2.x + f2.y, f3.x + f3.y);
        }
        *(float4*)&xst[tid][0] = make_float4(xv0, xv1, xv2, xv3);
        __syncthreads();

        if (tid < 256) {
            float2 R0 = *(const float2*)&gsumP[0][jj][cb0];
            float2 R1 = *(const float2*)&gsumP[1][jj][cb0];
            float2 Z0 = *(const float2*)&gsumP[0][128 + jj][cb0];
            float2 Z1 = *(const float2*)&gsumP[1][128 + jj][cb0];
            float2 N0 = *(const float2*)&gsumP[0][256 + jj][cb0];
            float2 N1 = *(const float2*)&gsumP[1][256 + jj][cb0];
            float2 XR = *(const float2*)&xst[jj][cb0];
            float2 XZ = *(const float2*)&xst[128 + jj][cb0];
            float2 XN = *(const float2*)&xst[256 + jj][cb0];

            const float r0 = sigmf(R0.x + R1.x + XR.x + br);
            const float z0 = sigmf(Z0.x + Z1.x + XZ.x + bz);
            const float n0 = tanh_fast(XN.x + r0 * (N0.x + N1.x + bn));
            const float h0 = (1.0f - z0) * n0 + z0 * hb[cb0][gj];
            hb[cb0][gj] = h0;

            const float r1 = sigmf(R0.y + R1.y + XR.y + br);
            const float z1 = sigmf(Z0.y + Z1.y + XZ.y + bz);
            const float n1 = tanh_fast(XN.y + r1 * (N0.y + N1.y + bn));
            const float h1 = (1.0f - z1) * n1 + z1 * hb[cb0 + 1][gj];
            hb[cb0 + 1][gj] = h1;

            *(float2*)&mail_out[(size_t)t * 1024 + 2 * tid] = make_float2(h0, h1);
            if (WRITE_Y) {
                y[(size_t)(bb0 + cb0)     * STRBY + (size_t)t * HH + gj] = h0;
                y[(size_t)(bb0 + cb0 + 1) * STRBY + (size_t)t * HH + gj] = h1;
            }
        }
        __syncthreads();
    }

    if (!WRITE_Y && tid < 256) {
        hout[(size_t)(bb0 + cb0)     * HH + gj] = hb[cb0][gj];
        hout[(size_t)(bb0 + cb0 + 1) * HH + gj] = hb[cb0 + 1][gj];
    }
}

// =====================================================================
// launch
// =====================================================================
extern "C" void kernel_launch(void* const* d_in, const int* in_sizes, int n_in,
                              void* d_out, int out_size)
{
    const float* obs   = (const float*)d_in[0];
    const float* w_ih0 = (const float*)d_in[1];
    const float* w_hh0 = (const float*)d_in[2];
    const float* b_ih0 = (const float*)d_in[3];
    const float* b_hh0 = (const float*)d_in[4];
    const float* w_ih1 = (const float*)d_in[5];
    const float* w_hh1 = (const float*)d_in[6];
    const float* b_ih1 = (const float*)d_in[7];
    const float* b_hh1 = (const float*)d_in[8];
    float* out = (float*)d_out;

    void* xg_p = nullptr;  cudaGetSymbolAddress(&xg_p, g_xg);
    void* y0_p = nullptr;  cudaGetSymbolAddress(&y0_p, g_y0);
    void* wt_p = nullptr;  cudaGetSymbolAddress(&wt_p, g_wth);
    void* ml_p = nullptr;  cudaGetSymbolAddress(&ml_p, g_mail);
    void* fl_p = nullptr;  cudaGetSymbolAddress(&fl_p, g_flag);
    float* xg   = (float*)xg_p;
    float* y0   = (float*)y0_p;
    float* wt   = (float*)wt_p;
    float* mail = (float*)ml_p;
    int*   flag0 = (int*)fl_p;
    int*   flag1 = flag0 + (size_t)64 * TT * 2;

    float* wA0 = wt;
    float* wB0 = wA0 + (size_t)NCOL * HH;
    float* wA1 = wB0 + (size_t)NCOL * HH;
    float* wB1 = wA1 + (size_t)NCOL * HH;

    cudaFuncSetAttribute(scan_kernel<true>,  cudaFuncAttributeMaxDynamicSharedMemorySize, SCAN_DSMEM);
    cudaFuncSetAttribute(scan_kernel<false>, cudaFuncAttributeMaxDynamicSharedMemorySize, SCAN_DSMEM);

    const int M = BB * TT;                 // 131072
    dim3 pgrid(G3 / TBN, M / TBM);         // (12, 1024)

    // resets + repacks first (both flag epochs pre-cleared; no mid-graph resets)
    reset_flags<<<64, 1024>>>(flag0);
    reset_flags<<<64, 1024>>>(flag1);
    repack_whh<<<G3, HH>>>(w_hh0, wA0, wB0);
    repack_whh<<<G3, HH>>>(w_hh1, wA1, wB1);

    // layer 0
    proj_tf32<<<pgrid, 256>>>(obs, w_ih0, b_ih0, xg, OBS);
    scan_kernel<true><<<2 * (BB / 4), NTH, SCAN_DSMEM>>>(xg, wA0, wB0, b_hh0, y0, nullptr, mail, flag0);
    // layer 1
    proj_tf32<<<pgrid, 256>>>(y0, w_ih1, b_ih1, xg, HH);
    scan_kernel<false><<<2 * (BB / 4), NTH, SCAN_DSMEM>>>(xg, wA1, wB1, b_hh1, nullptr, out, mail, flag1);
}